// round 11
// baseline (speedup 1.0000x reference)
#include <cuda_runtime.h>
#include <cuda_fp16.h>
#include <cstdint>

#define HW  4096
#define DIN 256
#define DK  64
#define DV  256
#define NB  4

// Scratch (device globals: no allocation allowed)
__device__ float    g_Q[NB * DK * HW];            // raw Q [b][k][hw] fp32
__device__ uint32_t g_K2H[NB * (DK/2) * HW];      // K hi, fp16x2 packed along dk
__device__ uint32_t g_K2L[NB * (DK/2) * HW];      // K lo residual
__device__ uint32_t g_V2[NB * DV * (HW/2)];       // V fp16x2 packed along hw

#define INVLN2 1.4426950408889634f

// ---------------------------------------------------------------------------
// helpers
// ---------------------------------------------------------------------------
__device__ __forceinline__ uint32_t h2u(__half2 h) {
    return *reinterpret_cast<uint32_t*>(&h);
}
__device__ __forceinline__ uint32_t packh2(float lo_elem, float hi_elem) {
    __half2 h = __floats2half2_rn(lo_elem, hi_elem);  // .x = low half
    return h2u(h);
}
__device__ __forceinline__ float ex2f(float x) {
    float r; asm("ex2.approx.f32 %0, %1;" : "=f"(r) : "f"(x)); return r;
}
__device__ __forceinline__ uint32_t smem_u32(const void* p) {
    uint32_t r;
    asm("{ .reg .u64 t; cvta.to.shared.u64 t, %1; cvt.u32.u64 %0, t; }"
        : "=r"(r) : "l"(p));
    return r;
}
__device__ __forceinline__ void cpa16(uint32_t dst, const uint32_t* src) {
    asm volatile("cp.async.cg.shared.global [%0], [%1], 16;"
                 :: "r"(dst), "l"(__cvta_generic_to_global(src)) : "memory");
}
#define CP_COMMIT() asm volatile("cp.async.commit_group;" ::: "memory")
#define CP_WAIT(n)  asm volatile("cp.async.wait_group %0;" :: "n"(n) : "memory")

// NOTE: deliberately NON-volatile — mma is a pure register op with no memory
// side effects. Volatile here forbids the compiler from interleaving the
// HMMA stream with MUFU/LDSM streams (the R8/R10 serialization bug).
__device__ __forceinline__ void mma_f16(float c[4], const uint32_t a[4],
                                        uint32_t b0, uint32_t b1) {
    asm("mma.sync.aligned.m16n8k16.row.col.f32.f16.f16.f32 "
        "{%0,%1,%2,%3}, {%4,%5,%6,%7}, {%8,%9}, {%0,%1,%2,%3};"
        : "+f"(c[0]), "+f"(c[1]), "+f"(c[2]), "+f"(c[3])
        : "r"(a[0]), "r"(a[1]), "r"(a[2]), "r"(a[3]), "r"(b0), "r"(b1));
}
__device__ __forceinline__ void ldsm_x4(uint32_t r[4], uint32_t addr) {
    asm volatile("ldmatrix.sync.aligned.m8n8.x4.shared.b16 {%0,%1,%2,%3}, [%4];"
        : "=r"(r[0]), "=r"(r[1]), "=r"(r[2]), "=r"(r[3]) : "r"(addr));
}
__device__ __forceinline__ void ldsm_x2(uint32_t& r0, uint32_t& r1, uint32_t addr) {
    asm volatile("ldmatrix.sync.aligned.m8n8.x2.shared.b16 {%0,%1}, [%2];"
        : "=r"(r0), "=r"(r1) : "r"(addr));
}

// ---------------------------------------------------------------------------
// Projection GEMM: Out[b][r][p] = sum_c W[r][c] * X[b][c][p]
// sel 0: raw fp32 -> g_Q
// sel 1: fp16 hi/lo split, packed along dk -> g_K2H / g_K2L
// sel 2: fp16, packed along hw -> g_V2
// ---------------------------------------------------------------------------
__global__ __launch_bounds__(256) void proj_kernel(
    const float* __restrict__ W, const float* __restrict__ X, int sel)
{
    __shared__ __align__(16) float Wt[16][68];
    __shared__ __align__(16) float Xt[16][64];

    const int t  = threadIdx.x;
    const int b  = blockIdx.z;
    const int r0 = blockIdx.y * 64;
    const int p0 = blockIdx.x * 64;

    const float* Xb = X + (size_t)b * DIN * HW;

    const int tr = t >> 4;
    const int tc = t & 15;

    float acc[4][4];
#pragma unroll
    for (int i = 0; i < 4; i++)
#pragma unroll
        for (int j = 0; j < 4; j++) acc[i][j] = 0.f;

    for (int ck = 0; ck < DIN; ck += 16) {
        const int wc = t & 15;
        const int wr = t >> 4;
#pragma unroll
        for (int i = 0; i < 4; i++)
            Wt[wc][wr + 16 * i] = W[(r0 + wr + 16 * i) * DIN + ck + wc];
        const int xp = t & 63;
        const int xc = t >> 6;
#pragma unroll
        for (int i = 0; i < 4; i++)
            Xt[xc + 4 * i][xp] = Xb[(size_t)(ck + xc + 4 * i) * HW + p0 + xp];
        __syncthreads();

#pragma unroll
        for (int c = 0; c < 16; c++) {
            float4 w4 = *(const float4*)&Wt[c][tr * 4];
            float4 x4 = *(const float4*)&Xt[c][tc * 4];
            float wa[4] = {w4.x, w4.y, w4.z, w4.w};
            float xa[4] = {x4.x, x4.y, x4.z, x4.w};
#pragma unroll
            for (int i = 0; i < 4; i++)
#pragma unroll
                for (int j = 0; j < 4; j++) acc[i][j] += wa[i] * xa[j];
        }
        __syncthreads();
    }

    if (sel == 0) {
        float* Ob = g_Q + (size_t)b * DK * HW;
#pragma unroll
        for (int i = 0; i < 4; i++) {
            float4 o = make_float4(acc[i][0], acc[i][1], acc[i][2], acc[i][3]);
            *(float4*)&Ob[(size_t)(r0 + tr * 4 + i) * HW + p0 + tc * 4] = o;
        }
    } else if (sel == 1) {
        uint32_t* KH = g_K2H + (size_t)b * (DK / 2) * HW;
        uint32_t* KL = g_K2L + (size_t)b * (DK / 2) * HW;
#pragma unroll
        for (int pr = 0; pr < 2; pr++) {
            const int kp = tr * 2 + pr;
#pragma unroll
            for (int j = 0; j < 4; j++) {
                float v0 = acc[pr * 2 + 0][j];
                float v1 = acc[pr * 2 + 1][j];
                __half hh0 = __float2half_rn(v0);
                __half hh1 = __float2half_rn(v1);
                float l0 = v0 - __half2float(hh0);
                float l1 = v1 - __half2float(hh1);
                size_t off = (size_t)kp * HW + p0 + tc * 4 + j;
                KH[off] = h2u(__halves2half2(hh0, hh1));
                KL[off] = packh2(l0, l1);
            }
        }
    } else {
        uint32_t* Vg = g_V2 + (size_t)b * DV * (HW / 2);
#pragma unroll
        for (int i = 0; i < 4; i++) {
            const size_t base = (size_t)(r0 + tr * 4 + i) * (HW / 2) + p0 / 2 + tc * 2;
            Vg[base]     = packh2(acc[i][0], acc[i][1]);
            Vg[base + 1] = packh2(acc[i][2], acc[i][3]);
        }
    }
}

// ---------------------------------------------------------------------------
// fp16 flash attention, deferred-AV pipeline with NON-VOLATILE mma (compiler
// interleaves exp/MUFU with AV HMMAs) + manual source interleave.
// 2 CTA barriers/tile. P double-buffered, V triple-buffered.
// CTA = (batch, 128-query tile), 512 threads, 64-key tiles.
// ---------------------------------------------------------------------------
#define QS2 36
#define KS2 68
#define VS2 36
#define PS2 36
#define WOFF_QH 0
#define WOFF_QL 4608
#define WOFF_KH 9216
#define WOFF_KL 11392
#define WOFF_V  13568        // 3 buffers x 9216
#define WOFF_P  41216        // 2 buffers x 4608
#define SMEM_WORDS 50432     // 201728 bytes

__global__ __launch_bounds__(512, 1) void attn_mma_kernel(float* __restrict__ Out)
{
    extern __shared__ uint32_t sm[];
    __shared__ __align__(16) float s_max[128][4];
    __shared__ float s_part[128][4];
    __shared__ float s_inv[128];

    uint32_t* QH = sm + WOFF_QH;
    uint32_t* QL = sm + WOFF_QL;
    uint32_t* KH = sm + WOFF_KH;
    uint32_t* KL = sm + WOFF_KL;

    const uint32_t SB     = smem_u32(sm);
    const uint32_t kh_dst = SB + WOFF_KH * 4;
    const uint32_t kl_dst = SB + WOFF_KL * 4;
    const uint32_t vv_dst0 = SB + WOFF_V * 4;     // + vbuf*9216*4
    const uint32_t pp_lm0  = SB + WOFF_P * 4;     // + pbuf*4608*4

    const int t    = threadIdx.x;
    const int w    = t >> 5;
    const int lane = t & 31;
    const int mg   = w >> 2;          // 0..3 : 32-row group
    const int ng   = w & 3;           // 0..3 : 16-col group (S) / 64-v group (AV)
    const int m0   = mg * 32;
    const int lr   = lane >> 2;       // groupID 0..7
    const int lc   = lane & 3;        // threadID-in-group 0..3
    const int b    = blockIdx.y;
    const int p0   = blockIdx.x * 128;

    const float*    Qb  = g_Q   + (size_t)b * DK * HW;
    const uint32_t* KHg = g_K2H + (size_t)b * (DK / 2) * HW;
    const uint32_t* KLg = g_K2L + (size_t)b * (DK / 2) * HW;
    const uint32_t* Vg  = g_V2  + (size_t)b * DV * (HW / 2);

    // ldmatrix per-thread address components
    const int  lq    = (lane & 7) + ((lane >> 3) & 1) * 8;  // row within m16
    const uint32_t colb = (uint32_t)(lane >> 4) * 16;       // 0 or 16 bytes
    const uint32_t qh_lm = SB + WOFF_QH * 4 + (uint32_t)(m0 + lq) * 144 + colb;
    const uint32_t ql_lm = SB + WOFF_QL * 4 + (uint32_t)(m0 + lq) * 144 + colb;
    const uint32_t pp_row = (uint32_t)(m0 + lq) * 144 + colb;
    const uint32_t vv_row = (uint32_t)(ng * 64 + (lane & 7)) * 144 +
                            (uint32_t)((lane >> 3) & 1) * 16;

    // cp.async coordinates
    const int kkp = t >> 4;            // K: 32 kp rows x 16 chunks = 1/thread
    const int kc4 = t & 15;

    // ---- prologue: issue K[0] then V[0] (separate groups) ----
    {
        uint32_t doff = (uint32_t)(kkp * KS2 + kc4 * 4) * 4;
        cpa16(kh_dst + doff, KHg + (size_t)kkp * HW + kc4 * 4);
        cpa16(kl_dst + doff, KLg + (size_t)kkp * HW + kc4 * 4);
        CP_COMMIT();
#pragma unroll
        for (int j = 0; j < 4; j++) {
            int id = t + j * 512;
            int row = id >> 3, c4 = id & 7;
            cpa16(vv_dst0 + (uint32_t)(row * VS2 + c4 * 4) * 4,
                  Vg + (size_t)row * (HW / 2) + c4 * 4);
        }
        CP_COMMIT();
    }

    // ---- load + split Q tile (scaled by 1/ln2; overlaps inflight copies) ----
#pragma unroll
    for (int i = 0; i < 8; i++) {
        int idx = t + i * 512;
        int mm = idx & 127, kp = idx >> 7;
        float q0 = Qb[(size_t)(2 * kp) * HW + p0 + mm] * INVLN2;
        float q1 = Qb[(size_t)(2 * kp + 1) * HW + p0 + mm] * INVLN2;
        __half h0 = __float2half_rn(q0);
        __half h1 = __float2half_rn(q1);
        QH[mm * QS2 + kp] = h2u(__halves2half2(h0, h1));
        QL[mm * QS2 + kp] = packh2(q0 - __half2float(h0), q1 - __half2float(h1));
    }

    float o[2][8][4];
#pragma unroll
    for (int mt = 0; mt < 2; mt++)
#pragma unroll
        for (int vt = 0; vt < 8; vt++)
#pragma unroll
            for (int j = 0; j < 4; j++) o[mt][vt][j] = 0.f;
    float rs[4]    = {0.f, 0.f, 0.f, 0.f};
    float runm[4]  = {-1e30f, -1e30f, -1e30f, -1e30f};
    float pcorr[4] = {1.f, 1.f, 1.f, 1.f};

    int vw = 1;   // V write buffer for tile kt+1
    int vr = 2;   // V read buffer for tile kt-1 ((kt-1)%3; dummy at kt=0)

    for (int kt = 0; kt < 64; kt++) {
        // ---- barrier A: K[kt] + V[kt-1] complete (newest group V[kt] pending) ----
        CP_WAIT(1);
        __syncthreads();

        // ---- S = Qh*Kh + Qh*Kl + Ql*Kh (fp16 split, fp32 accum) ----
        float c[2][2][4];
#pragma unroll
        for (int mt = 0; mt < 2; mt++)
#pragma unroll
            for (int nt = 0; nt < 2; nt++)
#pragma unroll
                for (int j = 0; j < 4; j++) c[mt][nt][j] = 0.f;

#pragma unroll
        for (int it = 0; it < 4; it++) {
            const int kw0 = it * 8 + lc;
            uint32_t ah[2][4], al[2][4];
#pragma unroll
            for (int mt = 0; mt < 2; mt++) {
                ldsm_x4(ah[mt], qh_lm + (uint32_t)mt * 2304 + (uint32_t)it * 32);
                ldsm_x4(al[mt], ql_lm + (uint32_t)mt * 2304 + (uint32_t)it * 32);
            }
#pragma unroll
            for (int nt = 0; nt < 2; nt++) {
                const int bc = ng * 16 + nt * 8 + lr;
                uint32_t bh0 = KH[kw0 * KS2 + bc];
                uint32_t bh1 = KH[(kw0 + 4) * KS2 + bc];
                uint32_t bl0 = KL[kw0 * KS2 + bc];
                uint32_t bl1 = KL[(kw0 + 4) * KS2 + bc];
#pragma unroll
                for (int mt = 0; mt < 2; mt++) {
                    mma_f16(c[mt][nt], ah[mt], bh0, bh1);
                    mma_f16(c[mt][nt], ah[mt], bl0, bl1);
                    mma_f16(c[mt][nt], al[mt], bh0, bh1);
                }
            }
        }

        // ---- warp-partial row max -> smem ----
#pragma unroll
        for (int mt = 0; mt < 2; mt++) {
            float mx0 = fmaxf(fmaxf(c[mt][0][0], c[mt][0][1]),
                              fmaxf(c[mt][1][0], c[mt][1][1]));
            float mx1 = fmaxf(fmaxf(c[mt][0][2], c[mt][0][3]),
                              fmaxf(c[mt][1][2], c[mt][1][3]));
            mx0 = fmaxf(mx0, __shfl_xor_sync(0xffffffffu, mx0, 1));
            mx0 = fmaxf(mx0, __shfl_xor_sync(0xffffffffu, mx0, 2));
            mx1 = fmaxf(mx1, __shfl_xor_sync(0xffffffffu, mx1, 1));
            mx1 = fmaxf(mx1, __shfl_xor_sync(0xffffffffu, mx1, 2));
            if (lc == 0) {
                s_max[m0 + mt * 16 + lr][ng]     = mx0;
                s_max[m0 + mt * 16 + lr + 8][ng] = mx1;
            }
        }
        __syncthreads();   // barrier B: s_max visible, K free, prev V-read done

        // ---- issue K[kt+1] then V[kt+1] (into vw buffer) ----
        if (kt < 63) {
            const int n0 = (kt + 1) * 64;
            uint32_t doff = (uint32_t)(kkp * KS2 + kc4 * 4) * 4;
            cpa16(kh_dst + doff, KHg + (size_t)kkp * HW + n0 + kc4 * 4);
            cpa16(kl_dst + doff, KLg + (size_t)kkp * HW + n0 + kc4 * 4);
            CP_COMMIT();
            const int nw0 = (kt + 1) * 32;
            const uint32_t vdst = vv_dst0 + (uint32_t)vw * 36864;
#pragma unroll
            for (int j = 0; j < 4; j++) {
                int id = t + j * 512;
                int row = id >> 3, c4 = id & 7;
                cpa16(vdst + (uint32_t)(row * VS2 + c4 * 4) * 4,
                      Vg + (size_t)row * (HW / 2) + nw0 + c4 * 4);
            }
            CP_COMMIT();
        }

        // ======= fused region: rescale + exp(kt) interleaved with AV(kt-1) ===
        float nm[4], corr[4];
#pragma unroll
        for (int s = 0; s < 4; s++) {
            const int row = m0 + (s >> 1) * 16 + (s & 1) * 8 + lr;
            float4 mv = *(const float4*)&s_max[row][0];
            float tmax = fmaxf(fmaxf(mv.x, mv.y), fmaxf(mv.z, mv.w));
            if (tmax > runm[s]) {
                corr[s] = ex2f(runm[s] - tmax);
                runm[s] = tmax;
                rs[s] *= corr[s];
            } else {
                corr[s] = 1.f;
            }
            nm[s] = runm[s];
        }

        // rescale O with PREVIOUS tile's corr (O excludes P[kt-1]V yet)
#pragma unroll
        for (int mt = 0; mt < 2; mt++) {
            if (pcorr[mt * 2] != 1.f || pcorr[mt * 2 + 1] != 1.f) {
#pragma unroll
                for (int vt = 0; vt < 8; vt++) {
                    o[mt][vt][0] *= pcorr[mt * 2];
                    o[mt][vt][1] *= pcorr[mt * 2];
                    o[mt][vt][2] *= pcorr[mt * 2 + 1];
                    o[mt][vt][3] *= pcorr[mt * 2 + 1];
                }
            }
        }

        uint32_t* PPw = sm + WOFF_P + (kt & 1) * 4608;
        const uint32_t pl = pp_lm0 + (uint32_t)((kt - 1) & 1) * 18432 + pp_row;
        const uint32_t vl = vv_dst0 + (uint32_t)vr * 36864 + vv_row;

        // interleave: 4 AV it-chunks braided with 4 exp quarter-chunks
#pragma unroll
        for (int it = 0; it < 4; it++) {
            // AV(kt-1) chunk (non-volatile mma -> scheduler overlaps with exp)
            if (kt > 0) {
                uint32_t a[2][4];
#pragma unroll
                for (int mt = 0; mt < 2; mt++)
                    ldsm_x4(a[mt], pl + (uint32_t)mt * 2304 + (uint32_t)it * 32);
#pragma unroll
                for (int vt = 0; vt < 8; vt++) {
                    uint32_t b0, b1;
                    ldsm_x2(b0, b1, vl + (uint32_t)vt * 1152 + (uint32_t)it * 32);
                    mma_f16(o[0][vt], a[0], b0, b1);
                    mma_f16(o[1][vt], a[1], b0, b1);
                }
            }
            // exp quarter: (mt, nt) = (it>>1, it&1)
            {
                const int mt = it >> 1, nt = it & 1;
                const int row = m0 + mt * 16 + lr;
                const float nm0 = nm[mt * 2], nm1 = nm[mt * 2 + 1];
                const int np = ng * 8 + nt * 4 + lc;
                float e0 = ex2f(c[mt][nt][0] - nm0);
                float e1 = ex2f(c[mt][nt][1] - nm0);
                float e2 = ex2f(c[mt][nt][2] - nm1);
                float e3 = ex2f(c[mt][nt][3] - nm1);
                PPw[row * PS2 + np]       = packh2(e0, e1);
                PPw[(row + 8) * PS2 + np] = packh2(e2, e3);
                rs[mt * 2 + 0] += e0 + e1;
                rs[mt * 2 + 1] += e2 + e3;
            }
        }

        // save corr for next region's O-rescale
#pragma unroll
        for (int s = 0; s < 4; s++) pcorr[s] = corr[s];

        vr = (vr == 2) ? 0 : vr + 1;
        vw = (vw == 2) ? 0 : vw + 1;
    }

    // ---- epilogue: final AV(63) ----
    CP_WAIT(0);
    __syncthreads();
#pragma unroll
    for (int mt = 0; mt < 2; mt++) {
        if (pcorr[mt * 2] != 1.f || pcorr[mt * 2 + 1] != 1.f) {
#pragma unroll
            for (int vt = 0; vt < 8; vt++) {
                o[mt][vt][0] *= pcorr[mt * 2];
                o[mt][vt][1] *= pcorr[mt * 2];
                o[mt][vt][2] *= pcorr[mt * 2 + 1];
                o[mt][vt][3] *= pcorr[mt * 2 + 1];
            }
        }
    }
    {
        const uint32_t pl = pp_lm0 + (uint32_t)(63 & 1) * 18432 + pp_row;
        const uint32_t vl = vv_dst0 + (uint32_t)(63 % 3) * 36864 + vv_row;
#pragma unroll
        for (int it = 0; it < 4; it++) {
            uint32_t a[2][4];
#pragma unroll
            for (int mt = 0; mt < 2; mt++)
                ldsm_x4(a[mt], pl + (uint32_t)mt * 2304 + (uint32_t)it * 32);
#pragma unroll
            for (int vt = 0; vt < 8; vt++) {
                uint32_t b0, b1;
                ldsm_x2(b0, b1, vl + (uint32_t)vt * 1152 + (uint32_t)it * 32);
                mma_f16(o[0][vt], a[0], b0, b1);
                mma_f16(o[1][vt], a[1], b0, b1);
            }
        }
    }

    // ---- rowsum reduction across lanes and ng groups ----
#pragma unroll
    for (int i = 0; i < 4; i++) {
        rs[i] += __shfl_xor_sync(0xffffffffu, rs[i], 1);
        rs[i] += __shfl_xor_sync(0xffffffffu, rs[i], 2);
    }
    if (lc == 0) {
#pragma unroll
        for (int i = 0; i < 4; i++) {
            int row = m0 + (i >> 1) * 16 + (i & 1) * 8 + lr;
            s_part[row][ng] = rs[i];
        }
    }
    __syncthreads();
    if (t < 128)
        s_inv[t] = 1.0f / (s_part[t][0] + s_part[t][1] + s_part[t][2] + s_part[t][3]);
    __syncthreads();

    // ---- normalize + store ----
    float* Ob = Out + (size_t)b * DV * HW;
#pragma unroll
    for (int mt = 0; mt < 2; mt++) {
        const int r = m0 + mt * 16 + lr;
        const float inv0 = s_inv[r];
        const float inv1 = s_inv[r + 8];
#pragma unroll
        for (int vt = 0; vt < 8; vt++) {
            const int v = ng * 64 + vt * 8 + 2 * lc;
            Ob[(size_t)v * HW + p0 + r]           = o[mt][vt][0] * inv0;
            Ob[(size_t)(v + 1) * HW + p0 + r]     = o[mt][vt][1] * inv0;
            Ob[(size_t)v * HW + p0 + r + 8]       = o[mt][vt][2] * inv1;
            Ob[(size_t)(v + 1) * HW + p0 + r + 8] = o[mt][vt][3] * inv1;
        }
    }
}

// ---------------------------------------------------------------------------
extern "C" void kernel_launch(void* const* d_in, const int* in_sizes, int n_in,
                              void* d_out, int out_size)
{
    const float* x  = (const float*)d_in[0];
    const float* qw = (const float*)d_in[1];
    const float* kw = (const float*)d_in[2];
    const float* vw = (const float*)d_in[3];
    float* out = (float*)d_out;

    proj_kernel<<<dim3(64, 1, NB), 256>>>(qw, x, 0);
    proj_kernel<<<dim3(64, 1, NB), 256>>>(kw, x, 1);
    proj_kernel<<<dim3(64, 4, NB), 256>>>(vw, x, 2);

    const size_t smem_bytes = (size_t)SMEM_WORDS * 4;
    cudaFuncSetAttribute(attn_mma_kernel,
                         cudaFuncAttributeMaxDynamicSharedMemorySize,
                         (int)smem_bytes);
    attn_mma_kernel<<<dim3(32, NB), 512, smem_bytes>>>(out);
}

// round 12
// speedup vs baseline: 1.0407x; 1.0407x over previous
#include <cuda_runtime.h>
#include <cuda_fp16.h>
#include <cstdint>

#define HW  4096
#define DIN 256
#define DK  64
#define DV  256
#define NB  4

// Scratch (device globals: no allocation allowed)
__device__ float    g_Q[NB * DK * HW];            // raw Q [b][k][hw] fp32
__device__ uint32_t g_K2H[NB * (DK/2) * HW];      // K hi, fp16x2 packed along dk
__device__ uint32_t g_K2L[NB * (DK/2) * HW];      // K lo residual
__device__ uint32_t g_V2[NB * DV * (HW/2)];       // V fp16x2 packed along hw

#define INVLN2 1.4426950408889634f

// ---------------------------------------------------------------------------
// helpers
// ---------------------------------------------------------------------------
__device__ __forceinline__ uint32_t h2u(__half2 h) {
    return *reinterpret_cast<uint32_t*>(&h);
}
__device__ __forceinline__ uint32_t packh2(float lo_elem, float hi_elem) {
    __half2 h = __floats2half2_rn(lo_elem, hi_elem);  // .x = low half
    return h2u(h);
}
__device__ __forceinline__ float ex2f(float x) {
    float r; asm("ex2.approx.f32 %0, %1;" : "=f"(r) : "f"(x)); return r;
}
__device__ __forceinline__ uint32_t smem_u32(const void* p) {
    uint32_t r;
    asm("{ .reg .u64 t; cvta.to.shared.u64 t, %1; cvt.u32.u64 %0, t; }"
        : "=r"(r) : "l"(p));
    return r;
}
__device__ __forceinline__ void cpa16(uint32_t dst, const uint32_t* src) {
    asm volatile("cp.async.cg.shared.global [%0], [%1], 16;"
                 :: "r"(dst), "l"(__cvta_generic_to_global(src)) : "memory");
}
#define CP_COMMIT() asm volatile("cp.async.commit_group;" ::: "memory")
#define CP_WAIT(n)  asm volatile("cp.async.wait_group %0;" :: "n"(n) : "memory")

// non-volatile: pure register op, lets the scheduler interleave freely
__device__ __forceinline__ void mma_f16(float c[4], const uint32_t a[4],
                                        uint32_t b0, uint32_t b1) {
    asm("mma.sync.aligned.m16n8k16.row.col.f32.f16.f16.f32 "
        "{%0,%1,%2,%3}, {%4,%5,%6,%7}, {%8,%9}, {%0,%1,%2,%3};"
        : "+f"(c[0]), "+f"(c[1]), "+f"(c[2]), "+f"(c[3])
        : "r"(a[0]), "r"(a[1]), "r"(a[2]), "r"(a[3]), "r"(b0), "r"(b1));
}
__device__ __forceinline__ void ldsm_x4(uint32_t r[4], uint32_t addr) {
    asm volatile("ldmatrix.sync.aligned.m8n8.x4.shared.b16 {%0,%1,%2,%3}, [%4];"
        : "=r"(r[0]), "=r"(r[1]), "=r"(r[2]), "=r"(r[3]) : "r"(addr));
}
__device__ __forceinline__ void ldsm_x2(uint32_t& r0, uint32_t& r1, uint32_t addr) {
    asm volatile("ldmatrix.sync.aligned.m8n8.x2.shared.b16 {%0,%1}, [%2];"
        : "=r"(r0), "=r"(r1) : "r"(addr));
}

// ---------------------------------------------------------------------------
// Projection GEMM: Out[b][r][p] = sum_c W[r][c] * X[b][c][p]
// sel 0: raw fp32 -> g_Q
// sel 1: fp16 hi/lo split, packed along dk -> g_K2H / g_K2L
// sel 2: fp16, packed along hw -> g_V2
// ---------------------------------------------------------------------------
__global__ __launch_bounds__(256) void proj_kernel(
    const float* __restrict__ W, const float* __restrict__ X, int sel)
{
    __shared__ __align__(16) float Wt[16][68];
    __shared__ __align__(16) float Xt[16][64];

    const int t  = threadIdx.x;
    const int b  = blockIdx.z;
    const int r0 = blockIdx.y * 64;
    const int p0 = blockIdx.x * 64;

    const float* Xb = X + (size_t)b * DIN * HW;

    const int tr = t >> 4;
    const int tc = t & 15;

    float acc[4][4];
#pragma unroll
    for (int i = 0; i < 4; i++)
#pragma unroll
        for (int j = 0; j < 4; j++) acc[i][j] = 0.f;

    for (int ck = 0; ck < DIN; ck += 16) {
        const int wc = t & 15;
        const int wr = t >> 4;
#pragma unroll
        for (int i = 0; i < 4; i++)
            Wt[wc][wr + 16 * i] = W[(r0 + wr + 16 * i) * DIN + ck + wc];
        const int xp = t & 63;
        const int xc = t >> 6;
#pragma unroll
        for (int i = 0; i < 4; i++)
            Xt[xc + 4 * i][xp] = Xb[(size_t)(ck + xc + 4 * i) * HW + p0 + xp];
        __syncthreads();

#pragma unroll
        for (int c = 0; c < 16; c++) {
            float4 w4 = *(const float4*)&Wt[c][tr * 4];
            float4 x4 = *(const float4*)&Xt[c][tc * 4];
            float wa[4] = {w4.x, w4.y, w4.z, w4.w};
            float xa[4] = {x4.x, x4.y, x4.z, x4.w};
#pragma unroll
            for (int i = 0; i < 4; i++)
#pragma unroll
                for (int j = 0; j < 4; j++) acc[i][j] += wa[i] * xa[j];
        }
        __syncthreads();
    }

    if (sel == 0) {
        float* Ob = g_Q + (size_t)b * DK * HW;
#pragma unroll
        for (int i = 0; i < 4; i++) {
            float4 o = make_float4(acc[i][0], acc[i][1], acc[i][2], acc[i][3]);
            *(float4*)&Ob[(size_t)(r0 + tr * 4 + i) * HW + p0 + tc * 4] = o;
        }
    } else if (sel == 1) {
        uint32_t* KH = g_K2H + (size_t)b * (DK / 2) * HW;
        uint32_t* KL = g_K2L + (size_t)b * (DK / 2) * HW;
#pragma unroll
        for (int pr = 0; pr < 2; pr++) {
            const int kp = tr * 2 + pr;
#pragma unroll
            for (int j = 0; j < 4; j++) {
                float v0 = acc[pr * 2 + 0][j];
                float v1 = acc[pr * 2 + 1][j];
                __half hh0 = __float2half_rn(v0);
                __half hh1 = __float2half_rn(v1);
                float l0 = v0 - __half2float(hh0);
                float l1 = v1 - __half2float(hh1);
                size_t off = (size_t)kp * HW + p0 + tc * 4 + j;
                KH[off] = h2u(__halves2half2(hh0, hh1));
                KL[off] = packh2(l0, l1);
            }
        }
    } else {
        uint32_t* Vg = g_V2 + (size_t)b * DV * (HW / 2);
#pragma unroll
        for (int i = 0; i < 4; i++) {
            const size_t base = (size_t)(r0 + tr * 4 + i) * (HW / 2) + p0 / 2 + tc * 2;
            Vg[base]     = packh2(acc[i][0], acc[i][1]);
            Vg[base + 1] = packh2(acc[i][2], acc[i][3]);
        }
    }
}

// ---------------------------------------------------------------------------
// fp16 flash attention — R9 pipeline, 64-query CTAs, 2 CTAs/SM (inter-CTA
// phase overlap: one CTA's softmax runs under the other's MMA).
// 256 threads = 8 warps; 64-key tiles.
//   S phase:  warp (mg = w>>2 in 0..1, ng = w&3) -> S[32m x 16n]
//   AV phase: warp (mg, ng) -> O[32m x 64v] (64 fp32 regs/thr)
// SMEM words (fp16x2): QH/QL [64m][32kp] s36, KH/KL [32kp][64n] s68,
//                      V [256v][32np] s36, P [64m][32np] s36
// ---------------------------------------------------------------------------
#define QS2 36
#define KS2 68
#define VS2 36
#define PS2 36
#define WOFF_QH 0
#define WOFF_QL 2304
#define WOFF_KH 4608
#define WOFF_KL 6784
#define WOFF_V  8960
#define WOFF_P  18176
#define SMEM_WORDS 20480     // 81920 bytes per CTA

__global__ __launch_bounds__(256, 2) void attn_mma_kernel(float* __restrict__ Out)
{
    extern __shared__ uint32_t sm[];
    __shared__ __align__(16) float s_max[64][4];
    __shared__ float s_part[64][4];
    __shared__ float s_inv[64];

    uint32_t* QH = sm + WOFF_QH;
    uint32_t* QL = sm + WOFF_QL;
    uint32_t* KH = sm + WOFF_KH;
    uint32_t* KL = sm + WOFF_KL;
    uint32_t* PP = sm + WOFF_P;

    const uint32_t SB     = smem_u32(sm);
    const uint32_t kh_dst = SB + WOFF_KH * 4;
    const uint32_t kl_dst = SB + WOFF_KL * 4;
    const uint32_t vv_dst = SB + WOFF_V * 4;

    const int t    = threadIdx.x;
    const int w    = t >> 5;
    const int lane = t & 31;
    const int mg   = w >> 2;          // 0..1 : 32-row group
    const int ng   = w & 3;           // 0..3 : 16-col group (S) / 64-v group (AV)
    const int m0   = mg * 32;
    const int lr   = lane >> 2;       // groupID 0..7
    const int lc   = lane & 3;        // threadID-in-group 0..3
    const int b    = blockIdx.y;
    const int p0   = blockIdx.x * 64;

    const float*    Qb  = g_Q   + (size_t)b * DK * HW;
    const uint32_t* KHg = g_K2H + (size_t)b * (DK / 2) * HW;
    const uint32_t* KLg = g_K2L + (size_t)b * (DK / 2) * HW;
    const uint32_t* Vg  = g_V2  + (size_t)b * DV * (HW / 2);

    // ldmatrix per-thread address components
    const int  lq    = (lane & 7) + ((lane >> 3) & 1) * 8;  // row within m16
    const uint32_t colb = (uint32_t)(lane >> 4) * 16;       // 0 or 16 bytes
    const uint32_t qh_lm = SB + WOFF_QH * 4 + (uint32_t)(m0 + lq) * 144 + colb;
    const uint32_t ql_lm = SB + WOFF_QL * 4 + (uint32_t)(m0 + lq) * 144 + colb;
    const uint32_t pp_lm = SB + WOFF_P  * 4 + (uint32_t)(m0 + lq) * 144 + colb;
    // V x2: matrix j = (lane>>3)&1; row v = ng*64 + (lane&7)
    const uint32_t vv_lm = SB + WOFF_V * 4 +
        (uint32_t)(ng * 64 + (lane & 7)) * 144 + (uint32_t)((lane >> 3) & 1) * 16;

    // cp.async coordinates (256 threads)
    // K: 32 kp rows x 16 chunks = 512 chunks -> 2 per thread
    // V: 256 rows x 8 chunks   = 2048 chunks -> 8 per thread

    // ---- issue K[0] then V[0] ----
    {
#pragma unroll
        for (int j = 0; j < 2; j++) {
            int id = t + j * 256;
            int row = id >> 4, c4 = id & 15;
            uint32_t doff = (uint32_t)(row * KS2 + c4 * 4) * 4;
            cpa16(kh_dst + doff, KHg + (size_t)row * HW + c4 * 4);
            cpa16(kl_dst + doff, KLg + (size_t)row * HW + c4 * 4);
        }
        CP_COMMIT();
#pragma unroll
        for (int j = 0; j < 8; j++) {
            int id = t + j * 256;
            int row = id >> 3, c4 = id & 7;
            cpa16(vv_dst + (uint32_t)(row * VS2 + c4 * 4) * 4,
                  Vg + (size_t)row * (HW / 2) + c4 * 4);
        }
        CP_COMMIT();
    }

    // ---- load + split Q tile [64 m][32 kp] (scaled by 1/ln2) ----
#pragma unroll
    for (int i = 0; i < 8; i++) {
        int idx = t + i * 256;
        int mm = idx & 63, kp = idx >> 6;
        float q0 = Qb[(size_t)(2 * kp) * HW + p0 + mm] * INVLN2;
        float q1 = Qb[(size_t)(2 * kp + 1) * HW + p0 + mm] * INVLN2;
        __half h0 = __float2half_rn(q0);
        __half h1 = __float2half_rn(q1);
        QH[mm * QS2 + kp] = h2u(__halves2half2(h0, h1));
        QL[mm * QS2 + kp] = packh2(q0 - __half2float(h0), q1 - __half2float(h1));
    }

    float o[2][8][4];
#pragma unroll
    for (int mt = 0; mt < 2; mt++)
#pragma unroll
        for (int vt = 0; vt < 8; vt++)
#pragma unroll
            for (int j = 0; j < 4; j++) o[mt][vt][j] = 0.f;
    float rs[4]   = {0.f, 0.f, 0.f, 0.f};
    float runm[4] = {-1e30f, -1e30f, -1e30f, -1e30f};

    for (int kt = 0; kt < 64; kt++) {
        // ---- wait K[kt] (V[kt] may stay in flight) ----
        CP_WAIT(1);
        __syncthreads();

        // ---- S = Qh*Kh + Qh*Kl + Ql*Kh (fp16 split, fp32 accum) ----
        float c[2][2][4];
#pragma unroll
        for (int mt = 0; mt < 2; mt++)
#pragma unroll
            for (int nt = 0; nt < 2; nt++)
#pragma unroll
                for (int j = 0; j < 4; j++) c[mt][nt][j] = 0.f;

#pragma unroll
        for (int it = 0; it < 4; it++) {
            const int kw0 = it * 8 + lc;
            uint32_t ah[2][4], al[2][4];
#pragma unroll
            for (int mt = 0; mt < 2; mt++) {
                ldsm_x4(ah[mt], qh_lm + (uint32_t)mt * 2304 + (uint32_t)it * 32);
                ldsm_x4(al[mt], ql_lm + (uint32_t)mt * 2304 + (uint32_t)it * 32);
            }
#pragma unroll
            for (int nt = 0; nt < 2; nt++) {
                const int bc = ng * 16 + nt * 8 + lr;
                uint32_t bh0 = KH[kw0 * KS2 + bc];
                uint32_t bh1 = KH[(kw0 + 4) * KS2 + bc];
                uint32_t bl0 = KL[kw0 * KS2 + bc];
                uint32_t bl1 = KL[(kw0 + 4) * KS2 + bc];
#pragma unroll
                for (int mt = 0; mt < 2; mt++) {
                    mma_f16(c[mt][nt], ah[mt], bh0, bh1);
                    mma_f16(c[mt][nt], ah[mt], bl0, bl1);
                    mma_f16(c[mt][nt], al[mt], bh0, bh1);
                }
            }
        }

        // ---- warp-partial row max -> smem ----
#pragma unroll
        for (int mt = 0; mt < 2; mt++) {
            float mx0 = fmaxf(fmaxf(c[mt][0][0], c[mt][0][1]),
                              fmaxf(c[mt][1][0], c[mt][1][1]));
            float mx1 = fmaxf(fmaxf(c[mt][0][2], c[mt][0][3]),
                              fmaxf(c[mt][1][2], c[mt][1][3]));
            mx0 = fmaxf(mx0, __shfl_xor_sync(0xffffffffu, mx0, 1));
            mx0 = fmaxf(mx0, __shfl_xor_sync(0xffffffffu, mx0, 2));
            mx1 = fmaxf(mx1, __shfl_xor_sync(0xffffffffu, mx1, 1));
            mx1 = fmaxf(mx1, __shfl_xor_sync(0xffffffffu, mx1, 2));
            if (lc == 0) {
                s_max[m0 + mt * 16 + lr][ng]     = mx0;
                s_max[m0 + mt * 16 + lr + 8][ng] = mx1;
            }
        }
        __syncthreads();   // K consumed + s_max visible

        // ---- issue K[kt+1] ----
        if (kt < 63) {
            const int n0 = (kt + 1) * 64;
#pragma unroll
            for (int j = 0; j < 2; j++) {
                int id = t + j * 256;
                int row = id >> 4, c4 = id & 15;
                uint32_t doff = (uint32_t)(row * KS2 + c4 * 4) * 4;
                cpa16(kh_dst + doff, KHg + (size_t)row * HW + n0 + c4 * 4);
                cpa16(kl_dst + doff, KLg + (size_t)row * HW + n0 + c4 * 4);
            }
            CP_COMMIT();
        }

        // ---- tile max, conditional online rescale (log2 domain) ----
        float nm[4], corr[4];
#pragma unroll
        for (int s = 0; s < 4; s++) {
            const int row = m0 + (s >> 1) * 16 + (s & 1) * 8 + lr;
            float4 mv = *(const float4*)&s_max[row][0];
            float tmax = fmaxf(fmaxf(mv.x, mv.y), fmaxf(mv.z, mv.w));
            if (tmax > runm[s]) {
                nm[s] = tmax;
                corr[s] = ex2f(runm[s] - tmax);
                rs[s] *= corr[s];
                runm[s] = tmax;
            } else {
                nm[s] = runm[s];
                corr[s] = 1.f;
            }
        }
#pragma unroll
        for (int mt = 0; mt < 2; mt++) {
            if (corr[mt * 2] != 1.f || corr[mt * 2 + 1] != 1.f) {
#pragma unroll
                for (int vt = 0; vt < 8; vt++) {
                    o[mt][vt][0] *= corr[mt * 2];
                    o[mt][vt][1] *= corr[mt * 2];
                    o[mt][vt][2] *= corr[mt * 2 + 1];
                    o[mt][vt][3] *= corr[mt * 2 + 1];
                }
            }
        }

        // ---- exp2, P -> SMEM fp16x2, rowsums ----
#pragma unroll
        for (int mt = 0; mt < 2; mt++) {
            const int row = m0 + mt * 16 + lr;
            const float nm0 = nm[mt * 2], nm1 = nm[mt * 2 + 1];
#pragma unroll
            for (int nt = 0; nt < 2; nt++) {
                const int np = ng * 8 + nt * 4 + lc;
                float e0 = ex2f(c[mt][nt][0] - nm0);
                float e1 = ex2f(c[mt][nt][1] - nm0);
                float e2 = ex2f(c[mt][nt][2] - nm1);
                float e3 = ex2f(c[mt][nt][3] - nm1);
                PP[row * PS2 + np]       = packh2(e0, e1);
                PP[(row + 8) * PS2 + np] = packh2(e2, e3);
                rs[mt * 2 + 0] += e0 + e1;
                rs[mt * 2 + 1] += e2 + e3;
            }
        }

        // ---- wait V[kt] (K[kt+1] stays in flight), make V+P visible ----
        if (kt < 63) { CP_WAIT(1); } else { CP_WAIT(0); }
        __syncthreads();

        // ---- O += P * V^T (ldmatrix fragments) ----
#pragma unroll
        for (int it = 0; it < 4; it++) {
            uint32_t a[2][4];
#pragma unroll
            for (int mt = 0; mt < 2; mt++)
                ldsm_x4(a[mt], pp_lm + (uint32_t)mt * 2304 + (uint32_t)it * 32);
#pragma unroll
            for (int vt = 0; vt < 8; vt++) {
                uint32_t b0, b1;
                ldsm_x2(b0, b1, vv_lm + (uint32_t)vt * 1152 + (uint32_t)it * 32);
                mma_f16(o[0][vt], a[0], b0, b1);
                mma_f16(o[1][vt], a[1], b0, b1);
            }
        }

        // ---- V/P consumed; issue V[kt+1] ----
        __syncthreads();
        if (kt < 63) {
            const int nw0 = (kt + 1) * 32;
#pragma unroll
            for (int j = 0; j < 8; j++) {
                int id = t + j * 256;
                int row = id >> 3, c4 = id & 7;
                cpa16(vv_dst + (uint32_t)(row * VS2 + c4 * 4) * 4,
                      Vg + (size_t)row * (HW / 2) + nw0 + c4 * 4);
            }
            CP_COMMIT();
        }
    }

    // ---- rowsum reduction across lanes and ng groups ----
#pragma unroll
    for (int i = 0; i < 4; i++) {
        rs[i] += __shfl_xor_sync(0xffffffffu, rs[i], 1);
        rs[i] += __shfl_xor_sync(0xffffffffu, rs[i], 2);
    }
    if (lc == 0) {
#pragma unroll
        for (int i = 0; i < 4; i++) {
            int row = m0 + (i >> 1) * 16 + (i & 1) * 8 + lr;
            s_part[row][ng] = rs[i];
        }
    }
    __syncthreads();
    if (t < 64)
        s_inv[t] = 1.0f / (s_part[t][0] + s_part[t][1] + s_part[t][2] + s_part[t][3]);
    __syncthreads();

    // ---- normalize + store ----
    float* Ob = Out + (size_t)b * DV * HW;
#pragma unroll
    for (int mt = 0; mt < 2; mt++) {
        const int r = m0 + mt * 16 + lr;
        const float inv0 = s_inv[r];
        const float inv1 = s_inv[r + 8];
#pragma unroll
        for (int vt = 0; vt < 8; vt++) {
            const int v = ng * 64 + vt * 8 + 2 * lc;
            Ob[(size_t)v * HW + p0 + r]           = o[mt][vt][0] * inv0;
            Ob[(size_t)(v + 1) * HW + p0 + r]     = o[mt][vt][1] * inv0;
            Ob[(size_t)v * HW + p0 + r + 8]       = o[mt][vt][2] * inv1;
            Ob[(size_t)(v + 1) * HW + p0 + r + 8] = o[mt][vt][3] * inv1;
        }
    }
}

// ---------------------------------------------------------------------------
extern "C" void kernel_launch(void* const* d_in, const int* in_sizes, int n_in,
                              void* d_out, int out_size)
{
    const float* x  = (const float*)d_in[0];
    const float* qw = (const float*)d_in[1];
    const float* kw = (const float*)d_in[2];
    const float* vw = (const float*)d_in[3];
    float* out = (float*)d_out;

    proj_kernel<<<dim3(64, 1, NB), 256>>>(qw, x, 0);
    proj_kernel<<<dim3(64, 1, NB), 256>>>(kw, x, 1);
    proj_kernel<<<dim3(64, 4, NB), 256>>>(vw, x, 2);

    const size_t smem_bytes = (size_t)SMEM_WORDS * 4;
    cudaFuncSetAttribute(attn_mma_kernel,
                         cudaFuncAttributeMaxDynamicSharedMemorySize,
                         (int)smem_bytes);
    attn_mma_kernel<<<dim3(64, NB), 256, smem_bytes>>>(out);
}

// round 14
// speedup vs baseline: 1.1517x; 1.1066x over previous
#include <cuda_runtime.h>
#include <cuda_fp16.h>
#include <cstdint>

#define HW  4096
#define DIN 256
#define DK  64
#define DV  256
#define NB  4

#define INVLN2 1.4426950408889634f

// Scratch (device globals: no allocation allowed)
__device__ uint32_t g_W2H[384 * 128];             // concat W hi (Q rows prescaled)
__device__ uint32_t g_W2L[384 * 128];             // concat W lo residual
__device__ uint32_t g_X2H[NB * 128 * HW];         // X hi, fp16x2 packed along c
__device__ uint32_t g_X2L[NB * 128 * HW];         // X lo residual
__device__ uint32_t g_Q2H[NB * HW * 32];          // Q hi  [b][hw][kp]
__device__ uint32_t g_Q2L[NB * HW * 32];          // Q lo  [b][hw][kp]
__device__ uint32_t g_K2H[NB * 32 * HW];          // K hi  [b][kp][hw]
__device__ uint32_t g_K2L[NB * 32 * HW];          // K lo  [b][kp][hw]
__device__ uint32_t g_V2[NB * DV * (HW / 2)];     // V fp16x2 packed along hw

// ---------------------------------------------------------------------------
// helpers
// ---------------------------------------------------------------------------
__device__ __forceinline__ uint32_t h2u(__half2 h) {
    return *reinterpret_cast<uint32_t*>(&h);
}
__device__ __forceinline__ uint32_t packh2(float lo_elem, float hi_elem) {
    __half2 h = __floats2half2_rn(lo_elem, hi_elem);  // .x = low half
    return h2u(h);
}
__device__ __forceinline__ float ex2f(float x) {
    float r; asm("ex2.approx.f32 %0, %1;" : "=f"(r) : "f"(x)); return r;
}
__device__ __forceinline__ uint32_t smem_u32(const void* p) {
    uint32_t r;
    asm("{ .reg .u64 t; cvta.to.shared.u64 t, %1; cvt.u32.u64 %0, t; }"
        : "=r"(r) : "l"(p));
    return r;
}
__device__ __forceinline__ void cpa16(uint32_t dst, const uint32_t* src) {
    asm volatile("cp.async.cg.shared.global [%0], [%1], 16;"
                 :: "r"(dst), "l"(__cvta_generic_to_global(src)) : "memory");
}
#define CP_COMMIT() asm volatile("cp.async.commit_group;" ::: "memory")
#define CP_WAIT(n)  asm volatile("cp.async.wait_group %0;" :: "n"(n) : "memory")

// non-volatile: pure register op, scheduler interleaves freely
__device__ __forceinline__ void mma_f16(float c[4], const uint32_t a[4],
                                        uint32_t b0, uint32_t b1) {
    asm("mma.sync.aligned.m16n8k16.row.col.f32.f16.f16.f32 "
        "{%0,%1,%2,%3}, {%4,%5,%6,%7}, {%8,%9}, {%0,%1,%2,%3};"
        : "+f"(c[0]), "+f"(c[1]), "+f"(c[2]), "+f"(c[3])
        : "r"(a[0]), "r"(a[1]), "r"(a[2]), "r"(a[3]), "r"(b0), "r"(b1));
}
__device__ __forceinline__ void ldsm_x4(uint32_t r[4], uint32_t addr) {
    asm volatile("ldmatrix.sync.aligned.m8n8.x4.shared.b16 {%0,%1,%2,%3}, [%4];"
        : "=r"(r[0]), "=r"(r[1]), "=r"(r[2]), "=r"(r[3]) : "r"(addr));
}
__device__ __forceinline__ void ldsm_x2(uint32_t& r0, uint32_t& r1, uint32_t addr) {
    asm volatile("ldmatrix.sync.aligned.m8n8.x2.shared.b16 {%0,%1}, [%2];"
        : "=r"(r0), "=r"(r1) : "r"(addr));
}

// ---------------------------------------------------------------------------
// prep_w: concat qw/kw/vw into W2H/W2L [384][128] fp16x2 pairs along c.
// Q rows (0..63) prescaled by 1/ln2.
// ---------------------------------------------------------------------------
__global__ __launch_bounds__(256) void prep_w(
    const float* __restrict__ qw, const float* __restrict__ kw,
    const float* __restrict__ vw)
{
    int idx = blockIdx.x * 256 + threadIdx.x;   // 0..49151
    int r = idx >> 7, cp = idx & 127;
    const float* src;
    int rr;
    if (r < 64)       { src = qw; rr = r; }
    else if (r < 128) { src = kw; rr = r - 64; }
    else              { src = vw; rr = r - 128; }
    float v0 = src[rr * 256 + 2 * cp];
    float v1 = src[rr * 256 + 2 * cp + 1];
    if (r < 64) { v0 *= INVLN2; v1 *= INVLN2; }
    __half h0 = __float2half_rn(v0), h1 = __float2half_rn(v1);
    g_W2H[idx] = h2u(__halves2half2(h0, h1));
    g_W2L[idx] = packh2(v0 - __half2float(h0), v1 - __half2float(h1));
}

// ---------------------------------------------------------------------------
// prep_x: X [b][256][4096] fp32 -> X2H/X2L [b][128][4096] fp16x2 pairs along c.
// ---------------------------------------------------------------------------
__global__ __launch_bounds__(256) void prep_x(const float* __restrict__ x)
{
    int p  = blockIdx.x * 256 + threadIdx.x;
    int cp = blockIdx.y;
    int b  = blockIdx.z;
    const float* xb = x + ((size_t)b * DIN + 2 * cp) * HW;
    float v0 = xb[p], v1 = xb[HW + p];
    __half h0 = __float2half_rn(v0), h1 = __float2half_rn(v1);
    size_t o = ((size_t)b * 128 + cp) * HW + p;
    g_X2H[o] = h2u(__halves2half2(h0, h1));
    g_X2L[o] = packh2(v0 - __half2float(h0), v1 - __half2float(h1));
}

// ---------------------------------------------------------------------------
// proj_mma: C[384 x 4096] = Wcat * X per batch, fp16 3-term split tensor GEMM.
// CTA tile 64 rows x 256 p (matches 8-warp mapping: warp = 32m x 64p).
// grid (16 ptiles, 6 rowgroups, NB). k = 256 channels (8 steps of 16 words).
// rg 0 -> Q rows, rg 1 -> K rows, rg 2..5 -> V rows ((rg-2)*64).
// Epilogue: stage C in smem, emit packed Q2H/Q2L, K2H/K2L, V2 layouts.
// ---------------------------------------------------------------------------
#define PWS 20    // W tile row stride (words); 80B
#define PXS 260   // X tile row stride (words); 1040B (16B-aligned)
#define PJ_BUF  10880                    // words per double-buffer half
#define PJ_WH(b_) ((b_) * PJ_BUF + 0)        // 64 x 20  = 1280 w
#define PJ_WL(b_) ((b_) * PJ_BUF + 1280)     // 1280 w
#define PJ_XH(b_) ((b_) * PJ_BUF + 2560)     // 16 x 260 = 4160 w
#define PJ_XL(b_) ((b_) * PJ_BUF + 6720)     // 4160 w
#define PJ_SMEM_WORDS (2 * PJ_BUF)           // 21760 words = 87040 B
// epilogue stage: 64 rows x 260 stride = 16640 w <= 21760 OK

__global__ __launch_bounds__(256, 2) void proj_mma()
{
    extern __shared__ uint32_t sm[];

    const uint32_t SB = smem_u32(sm);

    const int t    = threadIdx.x;
    const int w    = t >> 5;
    const int lane = t & 31;
    const int mg   = w >> 2;          // 0..1 : 32-row group
    const int ng   = w & 3;           // 0..3 : 64-col group
    const int m0   = mg * 32;
    const int lr   = lane >> 2;
    const int lc   = lane & 3;
    const int p0   = blockIdx.x * 256;
    const int rg   = blockIdx.y;      // 0..5
    const int b    = blockIdx.z;

    const uint32_t* WHg = g_W2H + (size_t)rg * 64 * 128;
    const uint32_t* WLg = g_W2L + (size_t)rg * 64 * 128;
    const uint32_t* XHg = g_X2H + (size_t)b * 128 * HW;
    const uint32_t* XLg = g_X2L + (size_t)b * 128 * HW;

    // ldmatrix A-frag address components
    const int  lq   = (lane & 7) + ((lane >> 3) & 1) * 8;
    const uint32_t colb = (uint32_t)(lane >> 4) * 16;

    // issue one k-step (W 64r x 16kp, X 16kp x 256p) into buffer bf
#define PJ_ISSUE(s_, bf_) do {                                                 \
        const int kw_ = (s_) * 16;                                             \
        const uint32_t whd_ = SB + PJ_WH(bf_) * 4;                             \
        const uint32_t wld_ = SB + PJ_WL(bf_) * 4;                             \
        {                                                                      \
            int row_ = t >> 2, c4_ = t & 3;   /* 64 rows x 4 chunks */         \
            uint32_t d_ = (uint32_t)(row_ * PWS + c4_ * 4) * 4;                \
            cpa16(whd_ + d_, WHg + (size_t)row_ * 128 + kw_ + c4_ * 4);        \
            cpa16(wld_ + d_, WLg + (size_t)row_ * 128 + kw_ + c4_ * 4);        \
        }                                                                      \
        const uint32_t xhd_ = SB + PJ_XH(bf_) * 4;                             \
        const uint32_t xld_ = SB + PJ_XL(bf_) * 4;                             \
        _Pragma("unroll")                                                      \
        for (int j_ = 0; j_ < 4; j_++) {      /* 16 rows x 64 chunks */        \
            int id_ = t + j_ * 256;                                            \
            int row_ = id_ >> 6, c4_ = id_ & 63;                               \
            uint32_t d_ = (uint32_t)(row_ * PXS + c4_ * 4) * 4;                \
            cpa16(xhd_ + d_, XHg + (size_t)(kw_ + row_) * HW + p0 + c4_ * 4);  \
            cpa16(xld_ + d_, XLg + (size_t)(kw_ + row_) * HW + p0 + c4_ * 4);  \
        }                                                                      \
        CP_COMMIT();                                                           \
    } while (0)

    PJ_ISSUE(0, 0);
    PJ_ISSUE(1, 1);

    float o[2][8][4];
#pragma unroll
    for (int mt = 0; mt < 2; mt++)
#pragma unroll
        for (int vt = 0; vt < 8; vt++)
#pragma unroll
            for (int j = 0; j < 4; j++) o[mt][vt][j] = 0.f;

    for (int s = 0; s < 8; s++) {
        if (s == 7) { CP_WAIT(0); } else { CP_WAIT(1); }
        __syncthreads();
        const int bf = s & 1;
        const uint32_t wh_lm = SB + PJ_WH(bf) * 4 + (uint32_t)(m0 + lq) * 80 + colb;
        const uint32_t wl_lm = SB + PJ_WL(bf) * 4 + (uint32_t)(m0 + lq) * 80 + colb;
        const uint32_t* XH = sm + PJ_XH(bf);
        const uint32_t* XL = sm + PJ_XL(bf);

#pragma unroll
        for (int it = 0; it < 2; it++) {
            const int kw0 = it * 8 + lc;
            uint32_t ah[2][4], al[2][4];
#pragma unroll
            for (int mt = 0; mt < 2; mt++) {
                ldsm_x4(ah[mt], wh_lm + (uint32_t)mt * 1280 + (uint32_t)it * 32);
                ldsm_x4(al[mt], wl_lm + (uint32_t)mt * 1280 + (uint32_t)it * 32);
            }
#pragma unroll
            for (int nt = 0; nt < 8; nt++) {
                const int bc = ng * 64 + nt * 8 + lr;
                uint32_t bh0 = XH[kw0 * PXS + bc];
                uint32_t bh1 = XH[(kw0 + 4) * PXS + bc];
                uint32_t bl0 = XL[kw0 * PXS + bc];
                uint32_t bl1 = XL[(kw0 + 4) * PXS + bc];
#pragma unroll
                for (int mt = 0; mt < 2; mt++) {
                    mma_f16(o[mt][nt], ah[mt], bh0, bh1);
                    mma_f16(o[mt][nt], ah[mt], bl0, bl1);
                    mma_f16(o[mt][nt], al[mt], bh0, bh1);
                }
            }
        }
        __syncthreads();
        if (s < 6) PJ_ISSUE(s + 2, bf);
    }

    // ---- epilogue: stage C [64 x 256] fp32 in smem (stride PXS) ----
    __syncthreads();
    float* ST = reinterpret_cast<float*>(sm);
#pragma unroll
    for (int mt = 0; mt < 2; mt++) {
        const int r = m0 + mt * 16 + lr;
#pragma unroll
        for (int vt = 0; vt < 8; vt++) {
            const int pcol = ng * 64 + vt * 8 + 2 * lc;
            ST[r * PXS + pcol]           = o[mt][vt][0];
            ST[r * PXS + pcol + 1]       = o[mt][vt][1];
            ST[(r + 8) * PXS + pcol]     = o[mt][vt][2];
            ST[(r + 8) * PXS + pcol + 1] = o[mt][vt][3];
        }
    }
    __syncthreads();

    if (rg == 0) {
        // Q rows -> g_Q2H/L [b][hw][32]
        for (int i = t; i < 8192; i += 256) {
            int p = i >> 5, kp = i & 31;
            float v0 = ST[(2 * kp) * PXS + p];
            float v1 = ST[(2 * kp + 1) * PXS + p];
            __half h0 = __float2half_rn(v0), h1 = __float2half_rn(v1);
            size_t off = ((size_t)b * HW + p0 + p) * 32 + kp;
            g_Q2H[off] = h2u(__halves2half2(h0, h1));
            g_Q2L[off] = packh2(v0 - __half2float(h0), v1 - __half2float(h1));
        }
    } else if (rg == 1) {
        // K rows -> g_K2H/L [b][32][hw]
        for (int i = t; i < 8192; i += 256) {
            int kp = i >> 8, p = i & 255;
            float v0 = ST[(2 * kp) * PXS + p];
            float v1 = ST[(2 * kp + 1) * PXS + p];
            __half h0 = __float2half_rn(v0), h1 = __float2half_rn(v1);
            size_t off = ((size_t)b * 32 + kp) * HW + p0 + p;
            g_K2H[off] = h2u(__halves2half2(h0, h1));
            g_K2L[off] = packh2(v0 - __half2float(h0), v1 - __half2float(h1));
        }
    } else {
        // V rows (rg-2)*64 .. +63 -> g_V2 [b][256][2048], packed along hw
        for (int i = t; i < 8192; i += 256) {
            int vl = i >> 7, p2 = i & 127;
            float v0 = ST[vl * PXS + 2 * p2];
            float v1 = ST[vl * PXS + 2 * p2 + 1];
            size_t off = ((size_t)b * 256 + (rg - 2) * 64 + vl) * (HW / 2)
                       + p0 / 2 + p2;
            g_V2[off] = packh2(v0, v1);
        }
    }
#undef PJ_ISSUE
}

// ---------------------------------------------------------------------------
// fp16 flash attention — R12 pipeline, 64-query CTAs, 2 CTAs/SM.
// Q preprocessed (scaled + split) by proj_mma -> pure cp.async prologue.
// ---------------------------------------------------------------------------
#define QS2 36
#define KS2 68
#define VS2 36
#define PS2 36
#define WOFF_QH 0
#define WOFF_QL 2304
#define WOFF_KH 4608
#define WOFF_KL 6784
#define WOFF_V  8960
#define WOFF_P  18176
#define SMEM_WORDS 20480     // 81920 bytes per CTA

__global__ __launch_bounds__(256, 2) void attn_mma_kernel(float* __restrict__ Out)
{
    extern __shared__ uint32_t sm[];
    __shared__ __align__(16) float s_max[64][4];
    __shared__ float s_part[64][4];
    __shared__ float s_inv[64];

    uint32_t* KH = sm + WOFF_KH;
    uint32_t* KL = sm + WOFF_KL;
    uint32_t* PP = sm + WOFF_P;

    const uint32_t SB     = smem_u32(sm);
    const uint32_t qh_dst = SB + WOFF_QH * 4;
    const uint32_t ql_dst = SB + WOFF_QL * 4;
    const uint32_t kh_dst = SB + WOFF_KH * 4;
    const uint32_t kl_dst = SB + WOFF_KL * 4;
    const uint32_t vv_dst = SB + WOFF_V * 4;

    const int t    = threadIdx.x;
    const int w    = t >> 5;
    const int lane = t & 31;
    const int mg   = w >> 2;
    const int ng   = w & 3;
    const int m0   = mg * 32;
    const int lr   = lane >> 2;
    const int lc   = lane & 3;
    const int b    = blockIdx.y;
    const int p0   = blockIdx.x * 64;

    const uint32_t* QHg = g_Q2H + ((size_t)b * HW + p0) * 32;
    const uint32_t* QLg = g_Q2L + ((size_t)b * HW + p0) * 32;
    const uint32_t* KHg = g_K2H + (size_t)b * 32 * HW;
    const uint32_t* KLg = g_K2L + (size_t)b * 32 * HW;
    const uint32_t* Vg  = g_V2  + (size_t)b * DV * (HW / 2);

    const int  lq   = (lane & 7) + ((lane >> 3) & 1) * 8;
    const uint32_t colb = (uint32_t)(lane >> 4) * 16;
    const uint32_t qh_lm = SB + WOFF_QH * 4 + (uint32_t)(m0 + lq) * 144 + colb;
    const uint32_t ql_lm = SB + WOFF_QL * 4 + (uint32_t)(m0 + lq) * 144 + colb;
    const uint32_t pp_lm = SB + WOFF_P  * 4 + (uint32_t)(m0 + lq) * 144 + colb;
    const uint32_t vv_lm = SB + WOFF_V * 4 +
        (uint32_t)(ng * 64 + (lane & 7)) * 144 + (uint32_t)((lane >> 3) & 1) * 16;

    // ---- prologue: Q group, K[0] group, V[0] group ----
    {
#pragma unroll
        for (int j = 0; j < 2; j++) {
            int id = t + j * 256;
            int row = id >> 3, c4 = id & 7;
            uint32_t doff = (uint32_t)(row * QS2 + c4 * 4) * 4;
            cpa16(qh_dst + doff, QHg + (size_t)row * 32 + c4 * 4);
            cpa16(ql_dst + doff, QLg + (size_t)row * 32 + c4 * 4);
        }
        CP_COMMIT();
#pragma unroll
        for (int j = 0; j < 2; j++) {
            int id = t + j * 256;
            int row = id >> 4, c4 = id & 15;
            uint32_t doff = (uint32_t)(row * KS2 + c4 * 4) * 4;
            cpa16(kh_dst + doff, KHg + (size_t)row * HW + c4 * 4);
            cpa16(kl_dst + doff, KLg + (size_t)row * HW + c4 * 4);
        }
        CP_COMMIT();
#pragma unroll
        for (int j = 0; j < 8; j++) {
            int id = t + j * 256;
            int row = id >> 3, c4 = id & 7;
            cpa16(vv_dst + (uint32_t)(row * VS2 + c4 * 4) * 4,
                  Vg + (size_t)row * (HW / 2) + c4 * 4);
        }
        CP_COMMIT();
    }

    float o[2][8][4];
#pragma unroll
    for (int mt = 0; mt < 2; mt++)
#pragma unroll
        for (int vt = 0; vt < 8; vt++)
#pragma unroll
            for (int j = 0; j < 4; j++) o[mt][vt][j] = 0.f;
    float rs[4]   = {0.f, 0.f, 0.f, 0.f};
    float runm[4] = {-1e30f, -1e30f, -1e30f, -1e30f};

    for (int kt = 0; kt < 64; kt++) {
        // ---- wait: Q + K[kt] ready (V[kt] may stay in flight) ----
        CP_WAIT(1);
        __syncthreads();

        // ---- S = Qh*Kh + Qh*Kl + Ql*Kh (fp16 split, fp32 accum) ----
        float c[2][2][4];
#pragma unroll
        for (int mt = 0; mt < 2; mt++)
#pragma unroll
            for (int nt = 0; nt < 2; nt++)
#pragma unroll
                for (int j = 0; j < 4; j++) c[mt][nt][j] = 0.f;

#pragma unroll
        for (int it = 0; it < 4; it++) {
            const int kw0 = it * 8 + lc;
            uint32_t ah[2][4], al[2][4];
#pragma unroll
            for (int mt = 0; mt < 2; mt++) {
                ldsm_x4(ah[mt], qh_lm + (uint32_t)mt * 2304 + (uint32_t)it * 32);
                ldsm_x4(al[mt], ql_lm + (uint32_t)mt * 2304 + (uint32_t)it * 32);
            }
#pragma unroll
            for (int nt = 0; nt < 2; nt++) {
                const int bc = ng * 16 + nt * 8 + lr;
                uint32_t bh0 = KH[kw0 * KS2 + bc];
                uint32_t bh1 = KH[(kw0 + 4) * KS2 + bc];
                uint32_t bl0 = KL[kw0 * KS2 + bc];
                uint32_t bl1 = KL[(kw0 + 4) * KS2 + bc];
#pragma unroll
                for (int mt = 0; mt < 2; mt++) {
                    mma_f16(c[mt][nt], ah[mt], bh0, bh1);
                    mma_f16(c[mt][nt], ah[mt], bl0, bl1);
                    mma_f16(c[mt][nt], al[mt], bh0, bh1);
                }
            }
        }

        // ---- warp-partial row max -> smem ----
#pragma unroll
        for (int mt = 0; mt < 2; mt++) {
            float mx0 = fmaxf(fmaxf(c[mt][0][0], c[mt][0][1]),
                              fmaxf(c[mt][1][0], c[mt][1][1]));
            float mx1 = fmaxf(fmaxf(c[mt][0][2], c[mt][0][3]),
                              fmaxf(c[mt][1][2], c[mt][1][3]));
            mx0 = fmaxf(mx0, __shfl_xor_sync(0xffffffffu, mx0, 1));
            mx0 = fmaxf(mx0, __shfl_xor_sync(0xffffffffu, mx0, 2));
            mx1 = fmaxf(mx1, __shfl_xor_sync(0xffffffffu, mx1, 1));
            mx1 = fmaxf(mx1, __shfl_xor_sync(0xffffffffu, mx1, 2));
            if (lc == 0) {
                s_max[m0 + mt * 16 + lr][ng]     = mx0;
                s_max[m0 + mt * 16 + lr + 8][ng] = mx1;
            }
        }
        __syncthreads();   // K consumed + s_max visible

        // ---- issue K[kt+1] ----
        if (kt < 63) {
            const int n0 = (kt + 1) * 64;
#pragma unroll
            for (int j = 0; j < 2; j++) {
                int id = t + j * 256;
                int row = id >> 4, c4 = id & 15;
                uint32_t doff = (uint32_t)(row * KS2 + c4 * 4) * 4;
                cpa16(kh_dst + doff, KHg + (size_t)row * HW + n0 + c4 * 4);
                cpa16(kl_dst + doff, KLg + (size_t)row * HW + n0 + c4 * 4);
            }
            CP_COMMIT();
        }

        // ---- tile max, conditional online rescale (log2 domain) ----
        float nm[4], corr[4];
#pragma unroll
        for (int s = 0; s < 4; s++) {
            const int row = m0 + (s >> 1) * 16 + (s & 1) * 8 + lr;
            float4 mv = *(const float4*)&s_max[row][0];
            float tmax = fmaxf(fmaxf(mv.x, mv.y), fmaxf(mv.z, mv.w));
            if (tmax > runm[s]) {
                nm[s] = tmax;
                corr[s] = ex2f(runm[s] - tmax);
                rs[s] *= corr[s];
                runm[s] = tmax;
            } else {
                nm[s] = runm[s];
                corr[s] = 1.f;
            }
        }
#pragma unroll
        for (int mt = 0; mt < 2; mt++) {
            if (corr[mt * 2] != 1.f || corr[mt * 2 + 1] != 1.f) {
#pragma unroll
                for (int vt = 0; vt < 8; vt++) {
                    o[mt][vt][0] *= corr[mt * 2];
                    o[mt][vt][1] *= corr[mt * 2];
                    o[mt][vt][2] *= corr[mt * 2 + 1];
                    o[mt][vt][3] *= corr[mt * 2 + 1];
                }
            }
        }

        // ---- exp2, P -> SMEM fp16x2, rowsums ----
#pragma unroll
        for (int mt = 0; mt < 2; mt++) {
            const int row = m0 + mt * 16 + lr;
            const float nm0 = nm[mt * 2], nm1 = nm[mt * 2 + 1];
#pragma unroll
            for (int nt = 0; nt < 2; nt++) {
                const int np = ng * 8 + nt * 4 + lc;
                float e0 = ex2f(c[mt][nt][0] - nm0);
                float e1 = ex2f(c[mt][nt][1] - nm0);
                float e2 = ex2f(c[mt][nt][2] - nm1);
                float e3 = ex2f(c[mt][nt][3] - nm1);
                PP[row * PS2 + np]       = packh2(e0, e1);
                PP[(row + 8) * PS2 + np] = packh2(e2, e3);
                rs[mt * 2 + 0] += e0 + e1;
                rs[mt * 2 + 1] += e2 + e3;
            }
        }

        // ---- wait V[kt] (K[kt+1] stays in flight), make V+P visible ----
        if (kt < 63) { CP_WAIT(1); } else { CP_WAIT(0); }
        __syncthreads();

        // ---- O += P * V^T (ldmatrix fragments) ----
#pragma unroll
        for (int it = 0; it < 4; it++) {
            uint32_t a[2][4];
#pragma unroll
            for (int mt = 0; mt < 2; mt++)
                ldsm_x4(a[mt], pp_lm + (uint32_t)mt * 2304 + (uint32_t)it * 32);
#pragma unroll
            for (int vt = 0; vt < 8; vt++) {
                uint32_t b0, b1;
                ldsm_x2(b0, b1, vv_lm + (uint32_t)vt * 1152 + (uint32_t)it * 32);
                mma_f16(o[0][vt], a[0], b0, b1);
                mma_f16(o[1][vt], a[1], b0, b1);
            }
        }

        // ---- V/P consumed; issue V[kt+1] ----
        __syncthreads();
        if (kt < 63) {
            const int nw0 = (kt + 1) * 32;
#pragma unroll
            for (int j = 0; j < 8; j++) {
                int id = t + j * 256;
                int row = id >> 3, c4 = id & 7;
                cpa16(vv_dst + (uint32_t)(row * VS2 + c4 * 4) * 4,
                      Vg + (size_t)row * (HW / 2) + nw0 + c4 * 4);
            }
            CP_COMMIT();
        }
    }

    // ---- rowsum reduction across lanes and ng groups ----
#pragma unroll
    for (int i = 0; i < 4; i++) {
        rs[i] += __shfl_xor_sync(0xffffffffu, rs[i], 1);
        rs[i] += __shfl_xor_sync(0xffffffffu, rs[i], 2);
    }
    if (lc == 0) {
#pragma unroll
        for (int i = 0; i < 4; i++) {
            int row = m0 + (i >> 1) * 16 + (i & 1) * 8 + lr;
            s_part[row][ng] = rs[i];
        }
    }
    __syncthreads();
    if (t < 64)
        s_inv[t] = 1.0f / (s_part[t][0] + s_part[t][1] + s_part[t][2] + s_part[t][3]);
    __syncthreads();

    // ---- normalize + store ----
    float* Ob = Out + (size_t)b * DV * HW;
#pragma unroll
    for (int mt = 0; mt < 2; mt++) {
        const int r = m0 + mt * 16 + lr;
        const float inv0 = s_inv[r];
        const float inv1 = s_inv[r + 8];
#pragma unroll
        for (int vt = 0; vt < 8; vt++) {
            const int v = ng * 64 + vt * 8 + 2 * lc;
            Ob[(size_t)v * HW + p0 + r]           = o[mt][vt][0] * inv0;
            Ob[(size_t)(v + 1) * HW + p0 + r]     = o[mt][vt][1] * inv0;
            Ob[(size_t)v * HW + p0 + r + 8]       = o[mt][vt][2] * inv1;
            Ob[(size_t)(v + 1) * HW + p0 + r + 8] = o[mt][vt][3] * inv1;
        }
    }
}

// ---------------------------------------------------------------------------
extern "C" void kernel_launch(void* const* d_in, const int* in_sizes, int n_in,
                              void* d_out, int out_size)
{
    const float* x  = (const float*)d_in[0];
    const float* qw = (const float*)d_in[1];
    const float* kw = (const float*)d_in[2];
    const float* vw = (const float*)d_in[3];
    float* out = (float*)d_out;

    prep_w<<<192, 256>>>(qw, kw, vw);
    prep_x<<<dim3(16, 128, NB), 256>>>(x);

    const size_t pj_smem = (size_t)PJ_SMEM_WORDS * 4;
    cudaFuncSetAttribute(proj_mma,
                         cudaFuncAttributeMaxDynamicSharedMemorySize,
                         (int)pj_smem);
    proj_mma<<<dim3(16, 6, NB), 256, pj_smem>>>();

    const size_t smem_bytes = (size_t)SMEM_WORDS * 4;
    cudaFuncSetAttribute(attn_mma_kernel,
                         cudaFuncAttributeMaxDynamicSharedMemorySize,
                         (int)smem_bytes);
    attn_mma_kernel<<<dim3(64, NB), 256, smem_bytes>>>(out);
}

// round 15
// speedup vs baseline: 1.1857x; 1.0295x over previous
#include <cuda_runtime.h>
#include <cuda_fp16.h>
#include <cstdint>

#define HW  4096
#define DIN 256
#define DK  64
#define DV  256
#define NB  4

#define INVLN2 1.4426950408889634f

// Scratch (device globals: no allocation allowed)
__device__ uint32_t g_W2H[384 * 128];             // concat W hi (Q rows prescaled)
__device__ uint32_t g_W2L[384 * 128];             // concat W lo residual
__device__ uint32_t g_X2H[NB * 128 * HW];         // X hi, fp16x2 packed along c
__device__ uint32_t g_X2L[NB * 128 * HW];         // X lo residual
__device__ uint32_t g_Q2H[NB * HW * 32];          // Q hi  [b][hw][kp]
__device__ uint32_t g_Q2L[NB * HW * 32];          // Q lo  [b][hw][kp]
__device__ uint32_t g_K2H[NB * HW * 32];          // K hi  [b][hw][kp]  (R15: Q-style)
__device__ uint32_t g_K2L[NB * HW * 32];          // K lo  [b][hw][kp]
__device__ uint32_t g_V2[NB * DV * (HW / 2)];     // V fp16x2 packed along hw

// ---------------------------------------------------------------------------
// helpers
// ---------------------------------------------------------------------------
__device__ __forceinline__ uint32_t h2u(__half2 h) {
    return *reinterpret_cast<uint32_t*>(&h);
}
__device__ __forceinline__ uint32_t packh2(float lo_elem, float hi_elem) {
    __half2 h = __floats2half2_rn(lo_elem, hi_elem);  // .x = low half
    return h2u(h);
}
__device__ __forceinline__ float ex2f(float x) {
    float r; asm("ex2.approx.f32 %0, %1;" : "=f"(r) : "f"(x)); return r;
}
__device__ __forceinline__ uint32_t smem_u32(const void* p) {
    uint32_t r;
    asm("{ .reg .u64 t; cvta.to.shared.u64 t, %1; cvt.u32.u64 %0, t; }"
        : "=r"(r) : "l"(p));
    return r;
}
__device__ __forceinline__ void cpa16(uint32_t dst, const uint32_t* src) {
    asm volatile("cp.async.cg.shared.global [%0], [%1], 16;"
                 :: "r"(dst), "l"(__cvta_generic_to_global(src)) : "memory");
}
#define CP_COMMIT() asm volatile("cp.async.commit_group;" ::: "memory")
#define CP_WAIT(n)  asm volatile("cp.async.wait_group %0;" :: "n"(n) : "memory")

// non-volatile: pure register op, scheduler interleaves freely
__device__ __forceinline__ void mma_f16(float c[4], const uint32_t a[4],
                                        uint32_t b0, uint32_t b1) {
    asm("mma.sync.aligned.m16n8k16.row.col.f32.f16.f16.f32 "
        "{%0,%1,%2,%3}, {%4,%5,%6,%7}, {%8,%9}, {%0,%1,%2,%3};"
        : "+f"(c[0]), "+f"(c[1]), "+f"(c[2]), "+f"(c[3])
        : "r"(a[0]), "r"(a[1]), "r"(a[2]), "r"(a[3]), "r"(b0), "r"(b1));
}
__device__ __forceinline__ void ldsm_x4(uint32_t r[4], uint32_t addr) {
    asm volatile("ldmatrix.sync.aligned.m8n8.x4.shared.b16 {%0,%1,%2,%3}, [%4];"
        : "=r"(r[0]), "=r"(r[1]), "=r"(r[2]), "=r"(r[3]) : "r"(addr));
}
__device__ __forceinline__ void ldsm_x2(uint32_t& r0, uint32_t& r1, uint32_t addr) {
    asm volatile("ldmatrix.sync.aligned.m8n8.x2.shared.b16 {%0,%1}, [%2];"
        : "=r"(r0), "=r"(r1) : "r"(addr));
}

// ---------------------------------------------------------------------------
// prep_w: concat qw/kw/vw into W2H/W2L [384][128] fp16x2 pairs along c.
// Q rows (0..63) prescaled by 1/ln2.
// ---------------------------------------------------------------------------
__global__ __launch_bounds__(256) void prep_w(
    const float* __restrict__ qw, const float* __restrict__ kw,
    const float* __restrict__ vw)
{
    int idx = blockIdx.x * 256 + threadIdx.x;   // 0..49151
    int r = idx >> 7, cp = idx & 127;
    const float* src;
    int rr;
    if (r < 64)       { src = qw; rr = r; }
    else if (r < 128) { src = kw; rr = r - 64; }
    else              { src = vw; rr = r - 128; }
    float v0 = src[rr * 256 + 2 * cp];
    float v1 = src[rr * 256 + 2 * cp + 1];
    if (r < 64) { v0 *= INVLN2; v1 *= INVLN2; }
    __half h0 = __float2half_rn(v0), h1 = __float2half_rn(v1);
    g_W2H[idx] = h2u(__halves2half2(h0, h1));
    g_W2L[idx] = packh2(v0 - __half2float(h0), v1 - __half2float(h1));
}

// ---------------------------------------------------------------------------
// prep_x: X [b][256][4096] fp32 -> X2H/X2L [b][128][4096] fp16x2 pairs along c.
// ---------------------------------------------------------------------------
__global__ __launch_bounds__(256) void prep_x(const float* __restrict__ x)
{
    int p  = blockIdx.x * 256 + threadIdx.x;
    int cp = blockIdx.y;
    int b  = blockIdx.z;
    const float* xb = x + ((size_t)b * DIN + 2 * cp) * HW;
    float v0 = xb[p], v1 = xb[HW + p];
    __half h0 = __float2half_rn(v0), h1 = __float2half_rn(v1);
    size_t o = ((size_t)b * 128 + cp) * HW + p;
    g_X2H[o] = h2u(__halves2half2(h0, h1));
    g_X2L[o] = packh2(v0 - __half2float(h0), v1 - __half2float(h1));
}

// ---------------------------------------------------------------------------
// proj_mma: C[384 x 4096] = Wcat * X per batch, fp16 3-term split tensor GEMM.
// CTA tile 64 rows x 256 p. grid (16 ptiles, 6 rowgroups, NB).
// rg 0 -> Q rows, rg 1 -> K rows (both emit [b][hw][kp]), rg 2..5 -> V rows.
// ---------------------------------------------------------------------------
#define PWS 20    // W tile row stride (words)
#define PXS 260   // X tile row stride (words)
#define PJ_BUF  10880
#define PJ_WH(b_) ((b_) * PJ_BUF + 0)
#define PJ_WL(b_) ((b_) * PJ_BUF + 1280)
#define PJ_XH(b_) ((b_) * PJ_BUF + 2560)
#define PJ_XL(b_) ((b_) * PJ_BUF + 6720)
#define PJ_SMEM_WORDS (2 * PJ_BUF)           // 21760 words = 87040 B

__global__ __launch_bounds__(256, 2) void proj_mma()
{
    extern __shared__ uint32_t sm[];

    const uint32_t SB = smem_u32(sm);

    const int t    = threadIdx.x;
    const int w    = t >> 5;
    const int lane = t & 31;
    const int mg   = w >> 2;
    const int ng   = w & 3;
    const int m0   = mg * 32;
    const int lr   = lane >> 2;
    const int lc   = lane & 3;
    const int p0   = blockIdx.x * 256;
    const int rg   = blockIdx.y;      // 0..5
    const int b    = blockIdx.z;

    const uint32_t* WHg = g_W2H + (size_t)rg * 64 * 128;
    const uint32_t* WLg = g_W2L + (size_t)rg * 64 * 128;
    const uint32_t* XHg = g_X2H + (size_t)b * 128 * HW;
    const uint32_t* XLg = g_X2L + (size_t)b * 128 * HW;

    const int  lq   = (lane & 7) + ((lane >> 3) & 1) * 8;
    const uint32_t colb = (uint32_t)(lane >> 4) * 16;

#define PJ_ISSUE(s_, bf_) do {                                                 \
        const int kw_ = (s_) * 16;                                             \
        const uint32_t whd_ = SB + PJ_WH(bf_) * 4;                             \
        const uint32_t wld_ = SB + PJ_WL(bf_) * 4;                             \
        {                                                                      \
            int row_ = t >> 2, c4_ = t & 3;                                    \
            uint32_t d_ = (uint32_t)(row_ * PWS + c4_ * 4) * 4;                \
            cpa16(whd_ + d_, WHg + (size_t)row_ * 128 + kw_ + c4_ * 4);        \
            cpa16(wld_ + d_, WLg + (size_t)row_ * 128 + kw_ + c4_ * 4);        \
        }                                                                      \
        const uint32_t xhd_ = SB + PJ_XH(bf_) * 4;                             \
        const uint32_t xld_ = SB + PJ_XL(bf_) * 4;                             \
        _Pragma("unroll")                                                      \
        for (int j_ = 0; j_ < 4; j_++) {                                       \
            int id_ = t + j_ * 256;                                            \
            int row_ = id_ >> 6, c4_ = id_ & 63;                               \
            uint32_t d_ = (uint32_t)(row_ * PXS + c4_ * 4) * 4;                \
            cpa16(xhd_ + d_, XHg + (size_t)(kw_ + row_) * HW + p0 + c4_ * 4);  \
            cpa16(xld_ + d_, XLg + (size_t)(kw_ + row_) * HW + p0 + c4_ * 4);  \
        }                                                                      \
        CP_COMMIT();                                                           \
    } while (0)

    PJ_ISSUE(0, 0);
    PJ_ISSUE(1, 1);

    float o[2][8][4];
#pragma unroll
    for (int mt = 0; mt < 2; mt++)
#pragma unroll
        for (int vt = 0; vt < 8; vt++)
#pragma unroll
            for (int j = 0; j < 4; j++) o[mt][vt][j] = 0.f;

    for (int s = 0; s < 8; s++) {
        if (s == 7) { CP_WAIT(0); } else { CP_WAIT(1); }
        __syncthreads();
        const int bf = s & 1;
        const uint32_t wh_lm = SB + PJ_WH(bf) * 4 + (uint32_t)(m0 + lq) * 80 + colb;
        const uint32_t wl_lm = SB + PJ_WL(bf) * 4 + (uint32_t)(m0 + lq) * 80 + colb;
        const uint32_t* XH = sm + PJ_XH(bf);
        const uint32_t* XL = sm + PJ_XL(bf);

#pragma unroll
        for (int it = 0; it < 2; it++) {
            const int kw0 = it * 8 + lc;
            uint32_t ah[2][4], al[2][4];
#pragma unroll
            for (int mt = 0; mt < 2; mt++) {
                ldsm_x4(ah[mt], wh_lm + (uint32_t)mt * 1280 + (uint32_t)it * 32);
                ldsm_x4(al[mt], wl_lm + (uint32_t)mt * 1280 + (uint32_t)it * 32);
            }
#pragma unroll
            for (int nt = 0; nt < 8; nt++) {
                const int bc = ng * 64 + nt * 8 + lr;
                uint32_t bh0 = XH[kw0 * PXS + bc];
                uint32_t bh1 = XH[(kw0 + 4) * PXS + bc];
                uint32_t bl0 = XL[kw0 * PXS + bc];
                uint32_t bl1 = XL[(kw0 + 4) * PXS + bc];
#pragma unroll
                for (int mt = 0; mt < 2; mt++) {
                    mma_f16(o[mt][nt], ah[mt], bh0, bh1);
                    mma_f16(o[mt][nt], ah[mt], bl0, bl1);
                    mma_f16(o[mt][nt], al[mt], bh0, bh1);
                }
            }
        }
        __syncthreads();
        if (s < 6) PJ_ISSUE(s + 2, bf);
    }

    // ---- epilogue: stage C [64 x 256] fp32 in smem (stride PXS) ----
    __syncthreads();
    float* ST = reinterpret_cast<float*>(sm);
#pragma unroll
    for (int mt = 0; mt < 2; mt++) {
        const int r = m0 + mt * 16 + lr;
#pragma unroll
        for (int vt = 0; vt < 8; vt++) {
            const int pcol = ng * 64 + vt * 8 + 2 * lc;
            ST[r * PXS + pcol]           = o[mt][vt][0];
            ST[r * PXS + pcol + 1]       = o[mt][vt][1];
            ST[(r + 8) * PXS + pcol]     = o[mt][vt][2];
            ST[(r + 8) * PXS + pcol + 1] = o[mt][vt][3];
        }
    }
    __syncthreads();

    if (rg <= 1) {
        // Q rows (rg==0) or K rows (rg==1) -> [b][hw][32] packed pairs
        uint32_t* GH = (rg == 0) ? g_Q2H : g_K2H;
        uint32_t* GL = (rg == 0) ? g_Q2L : g_K2L;
        for (int i = t; i < 8192; i += 256) {
            int p = i >> 5, kp = i & 31;
            float v0 = ST[(2 * kp) * PXS + p];
            float v1 = ST[(2 * kp + 1) * PXS + p];
            __half h0 = __float2half_rn(v0), h1 = __float2half_rn(v1);
            size_t off = ((size_t)b * HW + p0 + p) * 32 + kp;
            GH[off] = h2u(__halves2half2(h0, h1));
            GL[off] = packh2(v0 - __half2float(h0), v1 - __half2float(h1));
        }
    } else {
        // V rows (rg-2)*64 .. +63 -> g_V2 [b][256][2048], packed along hw
        for (int i = t; i < 8192; i += 256) {
            int vl = i >> 7, p2 = i & 127;
            float v0 = ST[vl * PXS + 2 * p2];
            float v1 = ST[vl * PXS + 2 * p2 + 1];
            size_t off = ((size_t)b * 256 + (rg - 2) * 64 + vl) * (HW / 2)
                       + p0 / 2 + p2;
            g_V2[off] = packh2(v0, v1);
        }
    }
#undef PJ_ISSUE
}

// ---------------------------------------------------------------------------
// fp16 flash attention — 64-query CTAs, 2 CTAs/SM; all fragments via ldmatrix
// (K now [n][kp] smem, same as Q — B-fragments via ldsm_x4).
// ---------------------------------------------------------------------------
#define QS2 36
#define KS2 36
#define VS2 36
#define PS2 36
#define WOFF_QH 0
#define WOFF_QL 2304
#define WOFF_KH 4608
#define WOFF_KL 6912
#define WOFF_V  9216
#define WOFF_P  18432
#define SMEM_WORDS 20736     // 82944 bytes per CTA

__global__ __launch_bounds__(256, 2) void attn_mma_kernel(float* __restrict__ Out)
{
    extern __shared__ uint32_t sm[];
    __shared__ __align__(16) float s_max[64][4];
    __shared__ float s_part[64][4];
    __shared__ float s_inv[64];

    uint32_t* PP = sm + WOFF_P;

    const uint32_t SB     = smem_u32(sm);
    const uint32_t qh_dst = SB + WOFF_QH * 4;
    const uint32_t ql_dst = SB + WOFF_QL * 4;
    const uint32_t kh_dst = SB + WOFF_KH * 4;
    const uint32_t kl_dst = SB + WOFF_KL * 4;
    const uint32_t vv_dst = SB + WOFF_V * 4;

    const int t    = threadIdx.x;
    const int w    = t >> 5;
    const int lane = t & 31;
    const int mg   = w >> 2;
    const int ng   = w & 3;
    const int m0   = mg * 32;
    const int lr   = lane >> 2;
    const int lc   = lane & 3;
    const int b    = blockIdx.y;
    const int p0   = blockIdx.x * 64;

    const uint32_t* QHg = g_Q2H + ((size_t)b * HW + p0) * 32;
    const uint32_t* QLg = g_Q2L + ((size_t)b * HW + p0) * 32;
    const uint32_t* KHg = g_K2H + (size_t)b * HW * 32;
    const uint32_t* KLg = g_K2L + (size_t)b * HW * 32;
    const uint32_t* Vg  = g_V2  + (size_t)b * DV * (HW / 2);

    const int  lq   = (lane & 7) + ((lane >> 3) & 1) * 8;
    const uint32_t colb = (uint32_t)(lane >> 4) * 16;
    const uint32_t qh_lm = SB + WOFF_QH * 4 + (uint32_t)(m0 + lq) * 144 + colb;
    const uint32_t ql_lm = SB + WOFF_QL * 4 + (uint32_t)(m0 + lq) * 144 + colb;
    const uint32_t pp_lm = SB + WOFF_P  * 4 + (uint32_t)(m0 + lq) * 144 + colb;
    // K B-fragment x4: lanes 0-7 nt0/k0-7, 8-15 nt0/k8-15, 16-23 nt1/k0-7, 24-31 nt1/k8-15
    const uint32_t kfrag_row = (uint32_t)(ng * 16 + (lane & 7) + ((lane >> 4) & 1) * 8);
    const uint32_t kfrag_col = (uint32_t)((lane >> 3) & 1) * 16;
    const uint32_t kh_lm = SB + WOFF_KH * 4 + kfrag_row * 144 + kfrag_col;
    const uint32_t kl_lm = SB + WOFF_KL * 4 + kfrag_row * 144 + kfrag_col;
    const uint32_t vv_lm = SB + WOFF_V * 4 +
        (uint32_t)(ng * 64 + (lane & 7)) * 144 + (uint32_t)((lane >> 3) & 1) * 16;

    // ---- prologue: Q group, K[0] group, V[0] group ----
    {
#pragma unroll
        for (int j = 0; j < 2; j++) {
            int id = t + j * 256;
            int row = id >> 3, c4 = id & 7;
            uint32_t doff = (uint32_t)(row * QS2 + c4 * 4) * 4;
            cpa16(qh_dst + doff, QHg + (size_t)row * 32 + c4 * 4);
            cpa16(ql_dst + doff, QLg + (size_t)row * 32 + c4 * 4);
        }
        CP_COMMIT();
#pragma unroll
        for (int j = 0; j < 2; j++) {
            int id = t + j * 256;
            int row = id >> 3, c4 = id & 7;
            uint32_t doff = (uint32_t)(row * KS2 + c4 * 4) * 4;
            cpa16(kh_dst + doff, KHg + (size_t)row * 32 + c4 * 4);
            cpa16(kl_dst + doff, KLg + (size_t)row * 32 + c4 * 4);
        }
        CP_COMMIT();
#pragma unroll
        for (int j = 0; j < 8; j++) {
            int id = t + j * 256;
            int row = id >> 3, c4 = id & 7;
            cpa16(vv_dst + (uint32_t)(row * VS2 + c4 * 4) * 4,
                  Vg + (size_t)row * (HW / 2) + c4 * 4);
        }
        CP_COMMIT();
    }

    float o[2][8][4];
#pragma unroll
    for (int mt = 0; mt < 2; mt++)
#pragma unroll
        for (int vt = 0; vt < 8; vt++)
#pragma unroll
            for (int j = 0; j < 4; j++) o[mt][vt][j] = 0.f;
    float rs[4]   = {0.f, 0.f, 0.f, 0.f};
    float runm[4] = {-1e30f, -1e30f, -1e30f, -1e30f};

    for (int kt = 0; kt < 64; kt++) {
        // ---- wait: Q + K[kt] ready (V[kt] may stay in flight) ----
        CP_WAIT(1);
        __syncthreads();

        // ---- S = Qh*Kh + Qh*Kl + Ql*Kh (fp16 split, fp32 accum) ----
        float c[2][2][4];
#pragma unroll
        for (int mt = 0; mt < 2; mt++)
#pragma unroll
            for (int nt = 0; nt < 2; nt++)
#pragma unroll
                for (int j = 0; j < 4; j++) c[mt][nt][j] = 0.f;

#pragma unroll
        for (int it = 0; it < 4; it++) {
            uint32_t ah[2][4], al[2][4];
#pragma unroll
            for (int mt = 0; mt < 2; mt++) {
                ldsm_x4(ah[mt], qh_lm + (uint32_t)mt * 2304 + (uint32_t)it * 32);
                ldsm_x4(al[mt], ql_lm + (uint32_t)mt * 2304 + (uint32_t)it * 32);
            }
            uint32_t kh4[4], kl4[4];
            ldsm_x4(kh4, kh_lm + (uint32_t)it * 32);
            ldsm_x4(kl4, kl_lm + (uint32_t)it * 32);
#pragma unroll
            for (int nt = 0; nt < 2; nt++) {
                uint32_t bh0 = kh4[nt * 2], bh1 = kh4[nt * 2 + 1];
                uint32_t bl0 = kl4[nt * 2], bl1 = kl4[nt * 2 + 1];
#pragma unroll
                for (int mt = 0; mt < 2; mt++) {
                    mma_f16(c[mt][nt], ah[mt], bh0, bh1);
                    mma_f16(c[mt][nt], ah[mt], bl0, bl1);
                    mma_f16(c[mt][nt], al[mt], bh0, bh1);
                }
            }
        }

        // ---- warp-partial row max -> smem ----
#pragma unroll
        for (int mt = 0; mt < 2; mt++) {
            float mx0 = fmaxf(fmaxf(c[mt][0][0], c[mt][0][1]),
                              fmaxf(c[mt][1][0], c[mt][1][1]));
            float mx1 = fmaxf(fmaxf(c[mt][0][2], c[mt][0][3]),
                              fmaxf(c[mt][1][2], c[mt][1][3]));
            mx0 = fmaxf(mx0, __shfl_xor_sync(0xffffffffu, mx0, 1));
            mx0 = fmaxf(mx0, __shfl_xor_sync(0xffffffffu, mx0, 2));
            mx1 = fmaxf(mx1, __shfl_xor_sync(0xffffffffu, mx1, 1));
            mx1 = fmaxf(mx1, __shfl_xor_sync(0xffffffffu, mx1, 2));
            if (lc == 0) {
                s_max[m0 + mt * 16 + lr][ng]     = mx0;
                s_max[m0 + mt * 16 + lr + 8][ng] = mx1;
            }
        }
        __syncthreads();   // K consumed + s_max visible

        // ---- issue K[kt+1] ----
        if (kt < 63) {
            const int n0 = (kt + 1) * 64;
#pragma unroll
            for (int j = 0; j < 2; j++) {
                int id = t + j * 256;
                int row = id >> 3, c4 = id & 7;
                uint32_t doff = (uint32_t)(row * KS2 + c4 * 4) * 4;
                cpa16(kh_dst + doff, KHg + (size_t)(n0 + row) * 32 + c4 * 4);
                cpa16(kl_dst + doff, KLg + (size_t)(n0 + row) * 32 + c4 * 4);
            }
            CP_COMMIT();
        }

        // ---- tile max, conditional online rescale (log2 domain) ----
        float nm[4], corr[4];
#pragma unroll
        for (int s = 0; s < 4; s++) {
            const int row = m0 + (s >> 1) * 16 + (s & 1) * 8 + lr;
            float4 mv = *(const float4*)&s_max[row][0];
            float tmax = fmaxf(fmaxf(mv.x, mv.y), fmaxf(mv.z, mv.w));
            if (tmax > runm[s]) {
                nm[s] = tmax;
                corr[s] = ex2f(runm[s] - tmax);
                rs[s] *= corr[s];
                runm[s] = tmax;
            } else {
                nm[s] = runm[s];
                corr[s] = 1.f;
            }
        }
#pragma unroll
        for (int mt = 0; mt < 2; mt++) {
            if (corr[mt * 2] != 1.f || corr[mt * 2 + 1] != 1.f) {
#pragma unroll
                for (int vt = 0; vt < 8; vt++) {
                    o[mt][vt][0] *= corr[mt * 2];
                    o[mt][vt][1] *= corr[mt * 2];
                    o[mt][vt][2] *= corr[mt * 2 + 1];
                    o[mt][vt][3] *= corr[mt * 2 + 1];
                }
            }
        }

        // ---- exp2, P -> SMEM fp16x2, rowsums ----
#pragma unroll
        for (int mt = 0; mt < 2; mt++) {
            const int row = m0 + mt * 16 + lr;
            const float nm0 = nm[mt * 2], nm1 = nm[mt * 2 + 1];
#pragma unroll
            for (int nt = 0; nt < 2; nt++) {
                const int np = ng * 8 + nt * 4 + lc;
                float e0 = ex2f(c[mt][nt][0] - nm0);
                float e1 = ex2f(c[mt][nt][1] - nm0);
                float e2 = ex2f(c[mt][nt][2] - nm1);
                float e3 = ex2f(c[mt][nt][3] - nm1);
                PP[row * PS2 + np]       = packh2(e0, e1);
                PP[(row + 8) * PS2 + np] = packh2(e2, e3);
                rs[mt * 2 + 0] += e0 + e1;
                rs[mt * 2 + 1] += e2 + e3;
            }
        }

        // ---- wait V[kt] (K[kt+1] stays in flight), make V+P visible ----
        if (kt < 63) { CP_WAIT(1); } else { CP_WAIT(0); }
        __syncthreads();

        // ---- O += P * V^T (ldmatrix fragments) ----
#pragma unroll
        for (int it = 0; it < 4; it++) {
            uint32_t a[2][4];
#pragma unroll
            for (int mt = 0; mt < 2; mt++)
                ldsm_x4(a[mt], pp_lm + (uint32_t)mt * 2304 + (uint32_t)it * 32);
#pragma unroll
            for (int vt = 0; vt < 8; vt++) {
                uint32_t b0, b1;
                ldsm_x2(b0, b1, vv_lm + (uint32_t)vt * 1152 + (uint32_t)it * 32);
                mma_f16(o[0][vt], a[0], b0, b1);
                mma_f16(o[1][vt], a[1], b0, b1);
            }
        }

        // ---- V/P consumed; issue V[kt+1] ----
        __syncthreads();
        if (kt < 63) {
            const int nw0 = (kt + 1) * 32;
#pragma unroll
            for (int j = 0; j < 8; j++) {
                int id = t + j * 256;
                int row = id >> 3, c4 = id & 7;
                cpa16(vv_dst + (uint32_t)(row * VS2 + c4 * 4) * 4,
                      Vg + (size_t)row * (HW / 2) + nw0 + c4 * 4);
            }
            CP_COMMIT();
        }
    }

    // ---- rowsum reduction across lanes and ng groups ----
#pragma unroll
    for (int i = 0; i < 4; i++) {
        rs[i] += __shfl_xor_sync(0xffffffffu, rs[i], 1);
        rs[i] += __shfl_xor_sync(0xffffffffu, rs[i], 2);
    }
    if (lc == 0) {
#pragma unroll
        for (int i = 0; i < 4; i++) {
            int row = m0 + (i >> 1) * 16 + (i & 1) * 8 + lr;
            s_part[row][ng] = rs[i];
        }
    }
    __syncthreads();
    if (t < 64)
        s_inv[t] = 1.0f / (s_part[t][0] + s_part[t][1] + s_part[t][2] + s_part[t][3]);
    __syncthreads();

    // ---- normalize + store ----
    float* Ob = Out + (size_t)b * DV * HW;
#pragma unroll
    for (int mt = 0; mt < 2; mt++) {
        const int r = m0 + mt * 16 + lr;
        const float inv0 = s_inv[r];
        const float inv1 = s_inv[r + 8];
#pragma unroll
        for (int vt = 0; vt < 8; vt++) {
            const int v = ng * 64 + vt * 8 + 2 * lc;
            Ob[(size_t)v * HW + p0 + r]           = o[mt][vt][0] * inv0;
            Ob[(size_t)(v + 1) * HW + p0 + r]     = o[mt][vt][1] * inv0;
            Ob[(size_t)v * HW + p0 + r + 8]       = o[mt][vt][2] * inv1;
            Ob[(size_t)(v + 1) * HW + p0 + r + 8] = o[mt][vt][3] * inv1;
        }
    }
}

// ---------------------------------------------------------------------------
extern "C" void kernel_launch(void* const* d_in, const int* in_sizes, int n_in,
                              void* d_out, int out_size)
{
    const float* x  = (const float*)d_in[0];
    const float* qw = (const float*)d_in[1];
    const float* kw = (const float*)d_in[2];
    const float* vw = (const float*)d_in[3];
    float* out = (float*)d_out;

    prep_w<<<192, 256>>>(qw, kw, vw);
    prep_x<<<dim3(16, 128, NB), 256>>>(x);

    const size_t pj_smem = (size_t)PJ_SMEM_WORDS * 4;
    cudaFuncSetAttribute(proj_mma,
                         cudaFuncAttributeMaxDynamicSharedMemorySize,
                         (int)pj_smem);
    proj_mma<<<dim3(16, 6, NB), 256, pj_smem>>>();

    const size_t smem_bytes = (size_t)SMEM_WORDS * 4;
    cudaFuncSetAttribute(attn_mma_kernel,
                         cudaFuncAttributeMaxDynamicSharedMemorySize,
                         (int)smem_bytes);
    attn_mma_kernel<<<dim3(64, NB), 256, smem_bytes>>>(out);
}

// round 16
// speedup vs baseline: 1.2534x; 1.0571x over previous
#include <cuda_runtime.h>
#include <cuda_fp16.h>
#include <cstdint>

#define HW  4096
#define DIN 256
#define DK  64
#define DV  256
#define NB  4

#define INVLN2 1.4426950408889634f

// Scratch (device globals: no allocation allowed)
__device__ uint32_t g_W2H[384 * 128];             // concat W hi (Q rows prescaled)
__device__ uint32_t g_W2L[384 * 128];             // concat W lo residual
__device__ uint32_t g_X2H[NB * 128 * HW];         // X hi, fp16x2 packed along c
__device__ uint32_t g_X2L[NB * 128 * HW];         // X lo residual
__device__ uint32_t g_Q2H[NB * HW * 32];          // Q hi  [b][hw][kp]
__device__ uint32_t g_Q2L[NB * HW * 32];          // Q lo  [b][hw][kp]
__device__ uint32_t g_K2H[NB * HW * 32];          // K hi  [b][hw][kp]
__device__ uint32_t g_K2L[NB * HW * 32];          // K lo  [b][hw][kp]
__device__ uint32_t g_V2[NB * DV * (HW / 2)];     // V fp16x2 packed along hw

// ---------------------------------------------------------------------------
// helpers
// ---------------------------------------------------------------------------
__device__ __forceinline__ uint32_t h2u(__half2 h) {
    return *reinterpret_cast<uint32_t*>(&h);
}
__device__ __forceinline__ uint32_t packh2(float lo_elem, float hi_elem) {
    __half2 h = __floats2half2_rn(lo_elem, hi_elem);  // .x = low half
    return h2u(h);
}
__device__ __forceinline__ float ex2f(float x) {
    float r; asm("ex2.approx.f32 %0, %1;" : "=f"(r) : "f"(x)); return r;
}
__device__ __forceinline__ uint32_t smem_u32(const void* p) {
    uint32_t r;
    asm("{ .reg .u64 t; cvta.to.shared.u64 t, %1; cvt.u32.u64 %0, t; }"
        : "=r"(r) : "l"(p));
    return r;
}
__device__ __forceinline__ void cpa16(uint32_t dst, const uint32_t* src) {
    asm volatile("cp.async.cg.shared.global [%0], [%1], 16;"
                 :: "r"(dst), "l"(__cvta_generic_to_global(src)) : "memory");
}
#define CP_COMMIT() asm volatile("cp.async.commit_group;" ::: "memory")
#define CP_WAIT(n)  asm volatile("cp.async.wait_group %0;" :: "n"(n) : "memory")

// non-volatile: pure register op, scheduler interleaves freely
__device__ __forceinline__ void mma_f16(float c[4], const uint32_t a[4],
                                        uint32_t b0, uint32_t b1) {
    asm("mma.sync.aligned.m16n8k16.row.col.f32.f16.f16.f32 "
        "{%0,%1,%2,%3}, {%4,%5,%6,%7}, {%8,%9}, {%0,%1,%2,%3};"
        : "+f"(c[0]), "+f"(c[1]), "+f"(c[2]), "+f"(c[3])
        : "r"(a[0]), "r"(a[1]), "r"(a[2]), "r"(a[3]), "r"(b0), "r"(b1));
}
__device__ __forceinline__ void ldsm_x4(uint32_t r[4], uint32_t addr) {
    asm volatile("ldmatrix.sync.aligned.m8n8.x4.shared.b16 {%0,%1,%2,%3}, [%4];"
        : "=r"(r[0]), "=r"(r[1]), "=r"(r[2]), "=r"(r[3]) : "r"(addr));
}

// ---------------------------------------------------------------------------
// prep_w: concat qw/kw/vw into W2H/W2L [384][128] fp16x2 pairs along c.
// Q rows (0..63) prescaled by 1/ln2.
// ---------------------------------------------------------------------------
__global__ __launch_bounds__(256) void prep_w(
    const float* __restrict__ qw, const float* __restrict__ kw,
    const float* __restrict__ vw)
{
    int idx = blockIdx.x * 256 + threadIdx.x;   // 0..49151
    int r = idx >> 7, cp = idx & 127;
    const float* src;
    int rr;
    if (r < 64)       { src = qw; rr = r; }
    else if (r < 128) { src = kw; rr = r - 64; }
    else              { src = vw; rr = r - 128; }
    float v0 = src[rr * 256 + 2 * cp];
    float v1 = src[rr * 256 + 2 * cp + 1];
    if (r < 64) { v0 *= INVLN2; v1 *= INVLN2; }
    __half h0 = __float2half_rn(v0), h1 = __float2half_rn(v1);
    g_W2H[idx] = h2u(__halves2half2(h0, h1));
    g_W2L[idx] = packh2(v0 - __half2float(h0), v1 - __half2float(h1));
}

// ---------------------------------------------------------------------------
// prep_x: X [b][256][4096] fp32 -> X2H/X2L [b][128][4096] fp16x2 pairs along c.
// ---------------------------------------------------------------------------
__global__ __launch_bounds__(256) void prep_x(const float* __restrict__ x)
{
    int p  = blockIdx.x * 256 + threadIdx.x;
    int cp = blockIdx.y;
    int b  = blockIdx.z;
    const float* xb = x + ((size_t)b * DIN + 2 * cp) * HW;
    float v0 = xb[p], v1 = xb[HW + p];
    __half h0 = __float2half_rn(v0), h1 = __float2half_rn(v1);
    size_t o = ((size_t)b * 128 + cp) * HW + p;
    g_X2H[o] = h2u(__halves2half2(h0, h1));
    g_X2L[o] = packh2(v0 - __half2float(h0), v1 - __half2float(h1));
}

// ---------------------------------------------------------------------------
// proj_mma: C[384 x 4096] = Wcat * X per batch, fp16 3-term split tensor GEMM.
// CTA tile 64 rows x 256 p. grid (16 ptiles, 6 rowgroups, NB).
// rg 0 -> Q rows, rg 1 -> K rows (both emit [b][hw][kp]), rg 2..5 -> V rows.
// ---------------------------------------------------------------------------
#define PWS 20    // W tile row stride (words)
#define PXS 260   // X tile row stride (words)
#define PJ_BUF  10880
#define PJ_WH(b_) ((b_) * PJ_BUF + 0)
#define PJ_WL(b_) ((b_) * PJ_BUF + 1280)
#define PJ_XH(b_) ((b_) * PJ_BUF + 2560)
#define PJ_XL(b_) ((b_) * PJ_BUF + 6720)
#define PJ_SMEM_WORDS (2 * PJ_BUF)           // 21760 words = 87040 B

__global__ __launch_bounds__(256, 2) void proj_mma()
{
    extern __shared__ uint32_t sm[];

    const uint32_t SB = smem_u32(sm);

    const int t    = threadIdx.x;
    const int w    = t >> 5;
    const int lane = t & 31;
    const int mg   = w >> 2;
    const int ng   = w & 3;
    const int m0   = mg * 32;
    const int lr   = lane >> 2;
    const int lc   = lane & 3;
    const int p0   = blockIdx.x * 256;
    const int rg   = blockIdx.y;      // 0..5
    const int b    = blockIdx.z;

    const uint32_t* WHg = g_W2H + (size_t)rg * 64 * 128;
    const uint32_t* WLg = g_W2L + (size_t)rg * 64 * 128;
    const uint32_t* XHg = g_X2H + (size_t)b * 128 * HW;
    const uint32_t* XLg = g_X2L + (size_t)b * 128 * HW;

    const int  lq   = (lane & 7) + ((lane >> 3) & 1) * 8;
    const uint32_t colb = (uint32_t)(lane >> 4) * 16;

#define PJ_ISSUE(s_, bf_) do {                                                 \
        const int kw_ = (s_) * 16;                                             \
        const uint32_t whd_ = SB + PJ_WH(bf_) * 4;                             \
        const uint32_t wld_ = SB + PJ_WL(bf_) * 4;                             \
        {                                                                      \
            int row_ = t >> 2, c4_ = t & 3;                                    \
            uint32_t d_ = (uint32_t)(row_ * PWS + c4_ * 4) * 4;                \
            cpa16(whd_ + d_, WHg + (size_t)row_ * 128 + kw_ + c4_ * 4);        \
            cpa16(wld_ + d_, WLg + (size_t)row_ * 128 + kw_ + c4_ * 4);        \
        }                                                                      \
        const uint32_t xhd_ = SB + PJ_XH(bf_) * 4;                             \
        const uint32_t xld_ = SB + PJ_XL(bf_) * 4;                             \
        _Pragma("unroll")                                                      \
        for (int j_ = 0; j_ < 4; j_++) {                                       \
            int id_ = t + j_ * 256;                                            \
            int row_ = id_ >> 6, c4_ = id_ & 63;                               \
            uint32_t d_ = (uint32_t)(row_ * PXS + c4_ * 4) * 4;                \
            cpa16(xhd_ + d_, XHg + (size_t)(kw_ + row_) * HW + p0 + c4_ * 4);  \
            cpa16(xld_ + d_, XLg + (size_t)(kw_ + row_) * HW + p0 + c4_ * 4);  \
        }                                                                      \
        CP_COMMIT();                                                           \
    } while (0)

    PJ_ISSUE(0, 0);
    PJ_ISSUE(1, 1);

    float o[2][8][4];
#pragma unroll
    for (int mt = 0; mt < 2; mt++)
#pragma unroll
        for (int vt = 0; vt < 8; vt++)
#pragma unroll
            for (int j = 0; j < 4; j++) o[mt][vt][j] = 0.f;

    for (int s = 0; s < 8; s++) {
        if (s == 7) { CP_WAIT(0); } else { CP_WAIT(1); }
        __syncthreads();
        const int bf = s & 1;
        const uint32_t wh_lm = SB + PJ_WH(bf) * 4 + (uint32_t)(m0 + lq) * 80 + colb;
        const uint32_t wl_lm = SB + PJ_WL(bf) * 4 + (uint32_t)(m0 + lq) * 80 + colb;
        const uint32_t* XH = sm + PJ_XH(bf);
        const uint32_t* XL = sm + PJ_XL(bf);

#pragma unroll
        for (int it = 0; it < 2; it++) {
            const int kw0 = it * 8 + lc;
            uint32_t ah[2][4], al[2][4];
#pragma unroll
            for (int mt = 0; mt < 2; mt++) {
                ldsm_x4(ah[mt], wh_lm + (uint32_t)mt * 1280 + (uint32_t)it * 32);
                ldsm_x4(al[mt], wl_lm + (uint32_t)mt * 1280 + (uint32_t)it * 32);
            }
#pragma unroll
            for (int nt = 0; nt < 8; nt++) {
                const int bc = ng * 64 + nt * 8 + lr;
                uint32_t bh0 = XH[kw0 * PXS + bc];
                uint32_t bh1 = XH[(kw0 + 4) * PXS + bc];
                uint32_t bl0 = XL[kw0 * PXS + bc];
                uint32_t bl1 = XL[(kw0 + 4) * PXS + bc];
#pragma unroll
                for (int mt = 0; mt < 2; mt++) {
                    mma_f16(o[mt][nt], ah[mt], bh0, bh1);
                    mma_f16(o[mt][nt], ah[mt], bl0, bl1);
                    mma_f16(o[mt][nt], al[mt], bh0, bh1);
                }
            }
        }
        __syncthreads();
        if (s < 6) PJ_ISSUE(s + 2, bf);
    }

    // ---- epilogue: stage C [64 x 256] fp32 in smem (stride PXS) ----
    __syncthreads();
    float* ST = reinterpret_cast<float*>(sm);
#pragma unroll
    for (int mt = 0; mt < 2; mt++) {
        const int r = m0 + mt * 16 + lr;
#pragma unroll
        for (int vt = 0; vt < 8; vt++) {
            const int pcol = ng * 64 + vt * 8 + 2 * lc;
            ST[r * PXS + pcol]           = o[mt][vt][0];
            ST[r * PXS + pcol + 1]       = o[mt][vt][1];
            ST[(r + 8) * PXS + pcol]     = o[mt][vt][2];
            ST[(r + 8) * PXS + pcol + 1] = o[mt][vt][3];
        }
    }
    __syncthreads();

    if (rg <= 1) {
        // Q rows (rg==0) or K rows (rg==1) -> [b][hw][32] packed pairs
        uint32_t* GH = (rg == 0) ? g_Q2H : g_K2H;
        uint32_t* GL = (rg == 0) ? g_Q2L : g_K2L;
        for (int i = t; i < 8192; i += 256) {
            int p = i >> 5, kp = i & 31;
            float v0 = ST[(2 * kp) * PXS + p];
            float v1 = ST[(2 * kp + 1) * PXS + p];
            __half h0 = __float2half_rn(v0), h1 = __float2half_rn(v1);
            size_t off = ((size_t)b * HW + p0 + p) * 32 + kp;
            GH[off] = h2u(__halves2half2(h0, h1));
            GL[off] = packh2(v0 - __half2float(h0), v1 - __half2float(h1));
        }
    } else {
        // V rows (rg-2)*64 .. +63 -> g_V2 [b][256][2048], packed along hw
        for (int i = t; i < 8192; i += 256) {
            int vl = i >> 7, p2 = i & 127;
            float v0 = ST[vl * PXS + 2 * p2];
            float v1 = ST[vl * PXS + 2 * p2 + 1];
            size_t off = ((size_t)b * 256 + (rg - 2) * 64 + vl) * (HW / 2)
                       + p0 / 2 + p2;
            g_V2[off] = packh2(v0, v1);
        }
    }
#undef PJ_ISSUE
}

// ---------------------------------------------------------------------------
// fp16 flash attention — 64-query CTAs, 2 CTAs/SM; ALL fragments via ldmatrix
// x4 (Q, K, P, and now V pairs). cp.async addresses hoisted to running offsets.
// ---------------------------------------------------------------------------
#define QS2 36
#define KS2 36
#define VS2 36
#define PS2 36
#define WOFF_QH 0
#define WOFF_QL 2304
#define WOFF_KH 4608
#define WOFF_KL 6912
#define WOFF_V  9216
#define WOFF_P  18432
#define SMEM_WORDS 20736     // 82944 bytes per CTA

__global__ __launch_bounds__(256, 2) void attn_mma_kernel(float* __restrict__ Out)
{
    extern __shared__ uint32_t sm[];
    __shared__ __align__(16) float s_max[64][4];
    __shared__ float s_part[64][4];
    __shared__ float s_inv[64];

    uint32_t* PP = sm + WOFF_P;

    const uint32_t SB = smem_u32(sm);

    const int t    = threadIdx.x;
    const int w    = t >> 5;
    const int lane = t & 31;
    const int mg   = w >> 2;
    const int ng   = w & 3;
    const int m0   = mg * 32;
    const int lr   = lane >> 2;
    const int lc   = lane & 3;
    const int b    = blockIdx.y;
    const int p0   = blockIdx.x * 64;

    const uint32_t* QHg = g_Q2H + ((size_t)b * HW + p0) * 32;
    const uint32_t* QLg = g_Q2L + ((size_t)b * HW + p0) * 32;
    const uint32_t* KHg = g_K2H + (size_t)b * HW * 32;
    const uint32_t* KLg = g_K2L + (size_t)b * HW * 32;
    const uint32_t* Vg  = g_V2  + (size_t)b * DV * (HW / 2);

    const int  lq   = (lane & 7) + ((lane >> 3) & 1) * 8;
    const uint32_t colb = (uint32_t)(lane >> 4) * 16;
    const uint32_t qh_lm = SB + WOFF_QH * 4 + (uint32_t)(m0 + lq) * 144 + colb;
    const uint32_t ql_lm = SB + WOFF_QL * 4 + (uint32_t)(m0 + lq) * 144 + colb;
    const uint32_t pp_lm = SB + WOFF_P  * 4 + (uint32_t)(m0 + lq) * 144 + colb;
    // K B-fragment x4: rows ng*16 + ((lane>>4)&1)*8 + (lane&7), col ((lane>>3)&1)*16
    const uint32_t kfrag_row = (uint32_t)(ng * 16 + (lane & 7) + ((lane >> 4) & 1) * 8);
    const uint32_t kfrag_col = (uint32_t)((lane >> 3) & 1) * 16;
    const uint32_t kh_lm = SB + WOFF_KH * 4 + kfrag_row * 144 + kfrag_col;
    const uint32_t kl_lm = SB + WOFF_KL * 4 + kfrag_row * 144 + kfrag_col;
    // V B-fragment x4 (two vt blocks per load): rows ng*64 + vt2*16 + ((lane>>4)&1)*8 + (lane&7)
    const uint32_t vfrag_row = (uint32_t)(ng * 64 + (lane & 7) + ((lane >> 4) & 1) * 8);
    const uint32_t vv4_lm = SB + WOFF_V * 4 + vfrag_row * 144 + kfrag_col;

    // ---- hoisted cp.async per-thread invariants ----
    const uint32_t qk_rc  = (uint32_t)((t >> 3) * 36 + (t & 7) * 4) * 4; // dst off (QS2==KS2==VS2)
    const uint32_t qk_src = (uint32_t)((t >> 3) * 32 + (t & 7) * 4);     // src elem off (32 w/row)
    const uint32_t v_src0 = (uint32_t)((t >> 3) * (HW / 2) + (t & 7) * 4);
    const uint32_t qh_d0 = SB + WOFF_QH * 4 + qk_rc;
    const uint32_t ql_d0 = SB + WOFF_QL * 4 + qk_rc;
    const uint32_t kh_d0 = SB + WOFF_KH * 4 + qk_rc;
    const uint32_t kl_d0 = SB + WOFF_KL * 4 + qk_rc;
    const uint32_t vv_d0 = SB + WOFF_V * 4 + qk_rc;

    // ---- prologue: Q group, K[0] group, V[0] group ----
    {
        cpa16(qh_d0,                 QHg + qk_src);
        cpa16(qh_d0 + 32 * 36 * 4,   QHg + qk_src + 32 * 32);
        cpa16(ql_d0,                 QLg + qk_src);
        cpa16(ql_d0 + 32 * 36 * 4,   QLg + qk_src + 32 * 32);
        CP_COMMIT();
        cpa16(kh_d0,                 KHg + qk_src);
        cpa16(kh_d0 + 32 * 36 * 4,   KHg + qk_src + 32 * 32);
        cpa16(kl_d0,                 KLg + qk_src);
        cpa16(kl_d0 + 32 * 36 * 4,   KLg + qk_src + 32 * 32);
        CP_COMMIT();
#pragma unroll
        for (int j = 0; j < 8; j++)
            cpa16(vv_d0 + (uint32_t)j * 32 * 36 * 4,
                  Vg + v_src0 + (uint32_t)j * 32 * (HW / 2));
        CP_COMMIT();
    }

    float o[2][8][4];
#pragma unroll
    for (int mt = 0; mt < 2; mt++)
#pragma unroll
        for (int vt = 0; vt < 8; vt++)
#pragma unroll
            for (int j = 0; j < 4; j++) o[mt][vt][j] = 0.f;
    float rs[4]   = {0.f, 0.f, 0.f, 0.f};
    float runm[4] = {-1e30f, -1e30f, -1e30f, -1e30f};

    uint32_t koff = 64 * 32;   // K src elem offset for tile kt+1
    uint32_t voff = 32;        // V src elem offset for tile kt+1

    for (int kt = 0; kt < 64; kt++) {
        // ---- wait: K[kt] ready (V[kt] may stay in flight) ----
        CP_WAIT(1);
        __syncthreads();

        // ---- S = Qh*Kh + Qh*Kl + Ql*Kh (fp16 split, fp32 accum) ----
        float c[2][2][4];
#pragma unroll
        for (int mt = 0; mt < 2; mt++)
#pragma unroll
            for (int nt = 0; nt < 2; nt++)
#pragma unroll
                for (int j = 0; j < 4; j++) c[mt][nt][j] = 0.f;

#pragma unroll
        for (int it = 0; it < 4; it++) {
            uint32_t ah[2][4], al[2][4];
#pragma unroll
            for (int mt = 0; mt < 2; mt++) {
                ldsm_x4(ah[mt], qh_lm + (uint32_t)mt * 2304 + (uint32_t)it * 32);
                ldsm_x4(al[mt], ql_lm + (uint32_t)mt * 2304 + (uint32_t)it * 32);
            }
            uint32_t kh4[4], kl4[4];
            ldsm_x4(kh4, kh_lm + (uint32_t)it * 32);
            ldsm_x4(kl4, kl_lm + (uint32_t)it * 32);
#pragma unroll
            for (int nt = 0; nt < 2; nt++) {
                uint32_t bh0 = kh4[nt * 2], bh1 = kh4[nt * 2 + 1];
                uint32_t bl0 = kl4[nt * 2], bl1 = kl4[nt * 2 + 1];
#pragma unroll
                for (int mt = 0; mt < 2; mt++) {
                    mma_f16(c[mt][nt], ah[mt], bh0, bh1);
                    mma_f16(c[mt][nt], ah[mt], bl0, bl1);
                    mma_f16(c[mt][nt], al[mt], bh0, bh1);
                }
            }
        }

        // ---- warp-partial row max -> smem ----
#pragma unroll
        for (int mt = 0; mt < 2; mt++) {
            float mx0 = fmaxf(fmaxf(c[mt][0][0], c[mt][0][1]),
                              fmaxf(c[mt][1][0], c[mt][1][1]));
            float mx1 = fmaxf(fmaxf(c[mt][0][2], c[mt][0][3]),
                              fmaxf(c[mt][1][2], c[mt][1][3]));
            mx0 = fmaxf(mx0, __shfl_xor_sync(0xffffffffu, mx0, 1));
            mx0 = fmaxf(mx0, __shfl_xor_sync(0xffffffffu, mx0, 2));
            mx1 = fmaxf(mx1, __shfl_xor_sync(0xffffffffu, mx1, 1));
            mx1 = fmaxf(mx1, __shfl_xor_sync(0xffffffffu, mx1, 2));
            if (lc == 0) {
                s_max[m0 + mt * 16 + lr][ng]     = mx0;
                s_max[m0 + mt * 16 + lr + 8][ng] = mx1;
            }
        }
        __syncthreads();   // K consumed + s_max visible

        // ---- issue K[kt+1] ----
        if (kt < 63) {
            cpa16(kh_d0,               KHg + qk_src + koff);
            cpa16(kh_d0 + 32 * 36 * 4, KHg + qk_src + koff + 32 * 32);
            cpa16(kl_d0,               KLg + qk_src + koff);
            cpa16(kl_d0 + 32 * 36 * 4, KLg + qk_src + koff + 32 * 32);
            CP_COMMIT();
            koff += 64 * 32;
        }

        // ---- tile max, conditional online rescale (log2 domain) ----
        float nm[4], corr[4];
#pragma unroll
        for (int s = 0; s < 4; s++) {
            const int row = m0 + (s >> 1) * 16 + (s & 1) * 8 + lr;
            float4 mv = *(const float4*)&s_max[row][0];
            float tmax = fmaxf(fmaxf(mv.x, mv.y), fmaxf(mv.z, mv.w));
            if (tmax > runm[s]) {
                nm[s] = tmax;
                corr[s] = ex2f(runm[s] - tmax);
                rs[s] *= corr[s];
                runm[s] = tmax;
            } else {
                nm[s] = runm[s];
                corr[s] = 1.f;
            }
        }
#pragma unroll
        for (int mt = 0; mt < 2; mt++) {
            if (corr[mt * 2] != 1.f || corr[mt * 2 + 1] != 1.f) {
#pragma unroll
                for (int vt = 0; vt < 8; vt++) {
                    o[mt][vt][0] *= corr[mt * 2];
                    o[mt][vt][1] *= corr[mt * 2];
                    o[mt][vt][2] *= corr[mt * 2 + 1];
                    o[mt][vt][3] *= corr[mt * 2 + 1];
                }
            }
        }

        // ---- exp2, P -> SMEM fp16x2, rowsums ----
#pragma unroll
        for (int mt = 0; mt < 2; mt++) {
            const int row = m0 + mt * 16 + lr;
            const float nm0 = nm[mt * 2], nm1 = nm[mt * 2 + 1];
#pragma unroll
            for (int nt = 0; nt < 2; nt++) {
                const int np = ng * 8 + nt * 4 + lc;
                float e0 = ex2f(c[mt][nt][0] - nm0);
                float e1 = ex2f(c[mt][nt][1] - nm0);
                float e2 = ex2f(c[mt][nt][2] - nm1);
                float e3 = ex2f(c[mt][nt][3] - nm1);
                PP[row * PS2 + np]       = packh2(e0, e1);
                PP[(row + 8) * PS2 + np] = packh2(e2, e3);
                rs[mt * 2 + 0] += e0 + e1;
                rs[mt * 2 + 1] += e2 + e3;
            }
        }

        // ---- wait V[kt] (K[kt+1] stays in flight), make V+P visible ----
        if (kt < 63) { CP_WAIT(1); } else { CP_WAIT(0); }
        __syncthreads();

        // ---- O += P * V^T (all-x4 ldmatrix fragments) ----
#pragma unroll
        for (int it = 0; it < 4; it++) {
            uint32_t a[2][4];
#pragma unroll
            for (int mt = 0; mt < 2; mt++)
                ldsm_x4(a[mt], pp_lm + (uint32_t)mt * 2304 + (uint32_t)it * 32);
#pragma unroll
            for (int vt2 = 0; vt2 < 4; vt2++) {
                uint32_t v4[4];
                ldsm_x4(v4, vv4_lm + (uint32_t)vt2 * 2304 + (uint32_t)it * 32);
                mma_f16(o[0][2 * vt2],     a[0], v4[0], v4[1]);
                mma_f16(o[1][2 * vt2],     a[1], v4[0], v4[1]);
                mma_f16(o[0][2 * vt2 + 1], a[0], v4[2], v4[3]);
                mma_f16(o[1][2 * vt2 + 1], a[1], v4[2], v4[3]);
            }
        }

        // ---- V/P consumed; issue V[kt+1] ----
        __syncthreads();
        if (kt < 63) {
#pragma unroll
            for (int j = 0; j < 8; j++)
                cpa16(vv_d0 + (uint32_t)j * 32 * 36 * 4,
                      Vg + v_src0 + voff + (uint32_t)j * 32 * (HW / 2));
            CP_COMMIT();
            voff += 32;
        }
    }

    // ---- rowsum reduction across lanes and ng groups ----
#pragma unroll
    for (int i = 0; i < 4; i++) {
        rs[i] += __shfl_xor_sync(0xffffffffu, rs[i], 1);
        rs[i] += __shfl_xor_sync(0xffffffffu, rs[i], 2);
    }
    if (lc == 0) {
#pragma unroll
        for (int i = 0; i < 4; i++) {
            int row = m0 + (i >> 1) * 16 + (i & 1) * 8 + lr;
            s_part[row][ng] = rs[i];
        }
    }
    __syncthreads();
    if (t < 64)
        s_inv[t] = 1.0f / (s_part[t][0] + s_part[t][1] + s_part[t][2] + s_part[t][3]);
    __syncthreads();

    // ---- normalize + store ----
    float* Ob = Out + (size_t)b * DV * HW;
#pragma unroll
    for (int mt = 0; mt < 2; mt++) {
        const int r = m0 + mt * 16 + lr;
        const float inv0 = s_inv[r];
        const float inv1 = s_inv[r + 8];
#pragma unroll
        for (int vt = 0; vt < 8; vt++) {
            const int v = ng * 64 + vt * 8 + 2 * lc;
            Ob[(size_t)v * HW + p0 + r]           = o[mt][vt][0] * inv0;
            Ob[(size_t)(v + 1) * HW + p0 + r]     = o[mt][vt][1] * inv0;
            Ob[(size_t)v * HW + p0 + r + 8]       = o[mt][vt][2] * inv1;
            Ob[(size_t)(v + 1) * HW + p0 + r + 8] = o[mt][vt][3] * inv1;
        }
    }
}

// ---------------------------------------------------------------------------
extern "C" void kernel_launch(void* const* d_in, const int* in_sizes, int n_in,
                              void* d_out, int out_size)
{
    const float* x  = (const float*)d_in[0];
    const float* qw = (const float*)d_in[1];
    const float* kw = (const float*)d_in[2];
    const float* vw = (const float*)d_in[3];
    float* out = (float*)d_out;

    prep_w<<<192, 256>>>(qw, kw, vw);
    prep_x<<<dim3(16, 128, NB), 256>>>(x);

    const size_t pj_smem = (size_t)PJ_SMEM_WORDS * 4;
    cudaFuncSetAttribute(proj_mma,
                         cudaFuncAttributeMaxDynamicSharedMemorySize,
                         (int)pj_smem);
    proj_mma<<<dim3(16, 6, NB), 256, pj_smem>>>();

    const size_t smem_bytes = (size_t)SMEM_WORDS * 4;
    cudaFuncSetAttribute(attn_mma_kernel,
                         cudaFuncAttributeMaxDynamicSharedMemorySize,
                         (int)smem_bytes);
    attn_mma_kernel<<<dim3(64, NB), 256, smem_bytes>>>(out);
}

// round 17
// speedup vs baseline: 1.3133x; 1.0478x over previous
#include <cuda_runtime.h>
#include <cuda_fp16.h>
#include <cstdint>

#define HW  4096
#define DIN 256
#define DK  64
#define DV  256
#define NB  4

#define INVLN2 1.4426950408889634f

// Scratch (device globals: no allocation allowed)
__device__ uint32_t g_W2H[384 * 128];             // concat W hi (Q rows prescaled)
__device__ uint32_t g_W2L[384 * 128];             // concat W lo residual
__device__ uint32_t g_X2H[NB * 128 * HW];         // X hi, fp16x2 packed along c
__device__ uint32_t g_X2L[NB * 128 * HW];         // X lo residual
__device__ uint32_t g_Q2H[NB * HW * 32];          // Q hi  [b][hw][kp]
__device__ uint32_t g_Q2L[NB * HW * 32];          // Q lo  [b][hw][kp]
__device__ uint32_t g_K2H[NB * HW * 32];          // K hi  [b][hw][kp]
__device__ uint32_t g_K2L[NB * HW * 32];          // K lo  [b][hw][kp]
__device__ uint32_t g_V2[NB * DV * (HW / 2)];     // V fp16x2 packed along hw

// ---------------------------------------------------------------------------
// helpers
// ---------------------------------------------------------------------------
__device__ __forceinline__ uint32_t h2u(__half2 h) {
    return *reinterpret_cast<uint32_t*>(&h);
}
__device__ __forceinline__ uint32_t packh2(float lo_elem, float hi_elem) {
    __half2 h = __floats2half2_rn(lo_elem, hi_elem);  // .x = low half
    return h2u(h);
}
__device__ __forceinline__ float ex2f(float x) {
    float r; asm("ex2.approx.f32 %0, %1;" : "=f"(r) : "f"(x)); return r;
}
__device__ __forceinline__ uint32_t smem_u32(const void* p) {
    uint32_t r;
    asm("{ .reg .u64 t; cvta.to.shared.u64 t, %1; cvt.u32.u64 %0, t; }"
        : "=r"(r) : "l"(p));
    return r;
}
__device__ __forceinline__ void cpa16(uint32_t dst, const uint32_t* src) {
    asm volatile("cp.async.cg.shared.global [%0], [%1], 16;"
                 :: "r"(dst), "l"(__cvta_generic_to_global(src)) : "memory");
}
#define CP_COMMIT() asm volatile("cp.async.commit_group;" ::: "memory")
#define CP_WAIT(n)  asm volatile("cp.async.wait_group %0;" :: "n"(n) : "memory")

// non-volatile: pure register op, scheduler interleaves freely
__device__ __forceinline__ void mma_f16(float c[4], const uint32_t a[4],
                                        uint32_t b0, uint32_t b1) {
    asm("mma.sync.aligned.m16n8k16.row.col.f32.f16.f16.f32 "
        "{%0,%1,%2,%3}, {%4,%5,%6,%7}, {%8,%9}, {%0,%1,%2,%3};"
        : "+f"(c[0]), "+f"(c[1]), "+f"(c[2]), "+f"(c[3])
        : "r"(a[0]), "r"(a[1]), "r"(a[2]), "r"(a[3]), "r"(b0), "r"(b1));
}
__device__ __forceinline__ void ldsm_x4(uint32_t r[4], uint32_t addr) {
    asm volatile("ldmatrix.sync.aligned.m8n8.x4.shared.b16 {%0,%1,%2,%3}, [%4];"
        : "=r"(r[0]), "=r"(r[1]), "=r"(r[2]), "=r"(r[3]) : "r"(addr));
}

// ---------------------------------------------------------------------------
// prep_all: fused prep_w + prep_x (blocks 0..191 = W, rest = X).
// W: concat qw/kw/vw -> W2H/W2L [384][128] pairs along c; Q rows prescaled.
// X: [b][256][4096] fp32 -> X2H/X2L [b][128][4096] pairs along c.
// ---------------------------------------------------------------------------
__global__ __launch_bounds__(256) void prep_all(
    const float* __restrict__ x,
    const float* __restrict__ qw, const float* __restrict__ kw,
    const float* __restrict__ vw)
{
    const int bid = blockIdx.x;
    if (bid < 192) {
        int idx = bid * 256 + threadIdx.x;   // 0..49151
        int r = idx >> 7, cp = idx & 127;
        const float* src;
        int rr;
        if (r < 64)       { src = qw; rr = r; }
        else if (r < 128) { src = kw; rr = r - 64; }
        else              { src = vw; rr = r - 128; }
        float v0 = src[rr * 256 + 2 * cp];
        float v1 = src[rr * 256 + 2 * cp + 1];
        if (r < 64) { v0 *= INVLN2; v1 *= INVLN2; }
        __half h0 = __float2half_rn(v0), h1 = __float2half_rn(v1);
        g_W2H[idx] = h2u(__halves2half2(h0, h1));
        g_W2L[idx] = packh2(v0 - __half2float(h0), v1 - __half2float(h1));
    } else {
        int xb = bid - 192;                  // 0..8191
        int p  = (xb & 15) * 256 + threadIdx.x;
        int cp = (xb >> 4) & 127;
        int b  = xb >> 11;
        const float* xbp = x + ((size_t)b * DIN + 2 * cp) * HW;
        float v0 = xbp[p], v1 = xbp[HW + p];
        __half h0 = __float2half_rn(v0), h1 = __float2half_rn(v1);
        size_t o = ((size_t)b * 128 + cp) * HW + p;
        g_X2H[o] = h2u(__halves2half2(h0, h1));
        g_X2L[o] = packh2(v0 - __half2float(h0), v1 - __half2float(h1));
    }
}

// ---------------------------------------------------------------------------
// proj_mma: C[384 x 4096] = Wcat * X per batch, fp16 3-term split tensor GEMM.
// R17: CTA tile 128 rows x 128 p (halves redundant X traffic vs 64x256).
// 8 warps: warp (mg = w&3, pg = w>>2) -> 32m x 64p (2 mt x 8 nt, 64 accs).
// grid (32 ptiles, 3 rowgroups, NB). rg0 -> Q rows 0-63 + K rows 64-127;
// rg1/rg2 -> V rows (rg-1)*128.
// ---------------------------------------------------------------------------
#define PWS 20    // W tile row stride (words)
#define PXS 132   // X tile row stride (words); 528 B (16B-aligned)
#define PJ_BUF  9344
#define PJ_WH(b_) ((b_) * PJ_BUF + 0)        // 128 x 20 = 2560 w
#define PJ_WL(b_) ((b_) * PJ_BUF + 2560)     // 2560 w
#define PJ_XH(b_) ((b_) * PJ_BUF + 5120)     // 16 x 132 = 2112 w
#define PJ_XL(b_) ((b_) * PJ_BUF + 7232)     // 2112 w
#define PJ_SMEM_WORDS (2 * PJ_BUF)           // 18688 words = 74752 B
// epilogue stage: 128 rows x 132 stride = 16896 w <= 18688 OK

__global__ __launch_bounds__(256, 2) void proj_mma()
{
    extern __shared__ uint32_t sm[];

    const uint32_t SB = smem_u32(sm);

    const int t    = threadIdx.x;
    const int w    = t >> 5;
    const int lane = t & 31;
    const int mg   = w & 3;           // 0..3 : 32-row group
    const int pg   = w >> 2;          // 0..1 : 64-col group
    const int m0   = mg * 32;
    const int lr   = lane >> 2;
    const int lc   = lane & 3;
    const int p0   = blockIdx.x * 128;
    const int rg   = blockIdx.y;      // 0..2
    const int b    = blockIdx.z;

    const uint32_t* WHg = g_W2H + (size_t)rg * 128 * 128;
    const uint32_t* WLg = g_W2L + (size_t)rg * 128 * 128;
    const uint32_t* XHg = g_X2H + (size_t)b * 128 * HW;
    const uint32_t* XLg = g_X2L + (size_t)b * 128 * HW;

    const int  lq   = (lane & 7) + ((lane >> 3) & 1) * 8;
    const uint32_t colb = (uint32_t)(lane >> 4) * 16;

#define PJ_ISSUE(s_, bf_) do {                                                 \
        const int kw_ = (s_) * 16;                                             \
        const uint32_t whd_ = SB + PJ_WH(bf_) * 4;                             \
        const uint32_t wld_ = SB + PJ_WL(bf_) * 4;                             \
        _Pragma("unroll")                                                      \
        for (int j_ = 0; j_ < 2; j_++) {     /* 128 rows x 4 chunks */         \
            int id_ = t + j_ * 256;                                            \
            int row_ = id_ >> 2, c4_ = id_ & 3;                                \
            uint32_t d_ = (uint32_t)(row_ * PWS + c4_ * 4) * 4;                \
            cpa16(whd_ + d_, WHg + (size_t)row_ * 128 + kw_ + c4_ * 4);        \
            cpa16(wld_ + d_, WLg + (size_t)row_ * 128 + kw_ + c4_ * 4);        \
        }                                                                      \
        const uint32_t xhd_ = SB + PJ_XH(bf_) * 4;                             \
        const uint32_t xld_ = SB + PJ_XL(bf_) * 4;                             \
        _Pragma("unroll")                                                      \
        for (int j_ = 0; j_ < 2; j_++) {     /* 16 rows x 32 chunks */         \
            int id_ = t + j_ * 256;                                            \
            int row_ = id_ >> 5, c4_ = id_ & 31;                               \
            uint32_t d_ = (uint32_t)(row_ * PXS + c4_ * 4) * 4;                \
            cpa16(xhd_ + d_, XHg + (size_t)(kw_ + row_) * HW + p0 + c4_ * 4);  \
            cpa16(xld_ + d_, XLg + (size_t)(kw_ + row_) * HW + p0 + c4_ * 4);  \
        }                                                                      \
        CP_COMMIT();                                                           \
    } while (0)

    PJ_ISSUE(0, 0);
    PJ_ISSUE(1, 1);

    float o[2][8][4];
#pragma unroll
    for (int mt = 0; mt < 2; mt++)
#pragma unroll
        for (int vt = 0; vt < 8; vt++)
#pragma unroll
            for (int j = 0; j < 4; j++) o[mt][vt][j] = 0.f;

    for (int s = 0; s < 8; s++) {
        if (s == 7) { CP_WAIT(0); } else { CP_WAIT(1); }
        __syncthreads();
        const int bf = s & 1;
        const uint32_t wh_lm = SB + PJ_WH(bf) * 4 + (uint32_t)(m0 + lq) * 80 + colb;
        const uint32_t wl_lm = SB + PJ_WL(bf) * 4 + (uint32_t)(m0 + lq) * 80 + colb;
        const uint32_t* XH = sm + PJ_XH(bf);
        const uint32_t* XL = sm + PJ_XL(bf);

#pragma unroll
        for (int it = 0; it < 2; it++) {
            const int kw0 = it * 8 + lc;
            uint32_t ah[2][4], al[2][4];
#pragma unroll
            for (int mt = 0; mt < 2; mt++) {
                ldsm_x4(ah[mt], wh_lm + (uint32_t)mt * 1280 + (uint32_t)it * 32);
                ldsm_x4(al[mt], wl_lm + (uint32_t)mt * 1280 + (uint32_t)it * 32);
            }
#pragma unroll
            for (int nt = 0; nt < 8; nt++) {
                const int bc = pg * 64 + nt * 8 + lr;
                uint32_t bh0 = XH[kw0 * PXS + bc];
                uint32_t bh1 = XH[(kw0 + 4) * PXS + bc];
                uint32_t bl0 = XL[kw0 * PXS + bc];
                uint32_t bl1 = XL[(kw0 + 4) * PXS + bc];
#pragma unroll
                for (int mt = 0; mt < 2; mt++) {
                    mma_f16(o[mt][nt], ah[mt], bh0, bh1);
                    mma_f16(o[mt][nt], ah[mt], bl0, bl1);
                    mma_f16(o[mt][nt], al[mt], bh0, bh1);
                }
            }
        }
        __syncthreads();
        if (s < 6) PJ_ISSUE(s + 2, bf);
    }

    // ---- epilogue: stage C [128 x 128] fp32 in smem (stride PXS) ----
    __syncthreads();
    float* ST = reinterpret_cast<float*>(sm);
#pragma unroll
    for (int mt = 0; mt < 2; mt++) {
        const int r = m0 + mt * 16 + lr;
#pragma unroll
        for (int vt = 0; vt < 8; vt++) {
            const int pcol = pg * 64 + vt * 8 + 2 * lc;
            ST[r * PXS + pcol]           = o[mt][vt][0];
            ST[r * PXS + pcol + 1]       = o[mt][vt][1];
            ST[(r + 8) * PXS + pcol]     = o[mt][vt][2];
            ST[(r + 8) * PXS + pcol + 1] = o[mt][vt][3];
        }
    }
    __syncthreads();

    if (rg == 0) {
        // rows 0-63 = Q, rows 64-127 = K -> [b][hw][32] packed pairs
        for (int i = t; i < 4096; i += 256) {
            int p = i >> 5, kp = i & 31;
            float v0 = ST[(2 * kp) * PXS + p];
            float v1 = ST[(2 * kp + 1) * PXS + p];
            __half h0 = __float2half_rn(v0), h1 = __float2half_rn(v1);
            size_t off = ((size_t)b * HW + p0 + p) * 32 + kp;
            g_Q2H[off] = h2u(__halves2half2(h0, h1));
            g_Q2L[off] = packh2(v0 - __half2float(h0), v1 - __half2float(h1));
        }
        for (int i = t; i < 4096; i += 256) {
            int p = i >> 5, kp = i & 31;
            float v0 = ST[(64 + 2 * kp) * PXS + p];
            float v1 = ST[(64 + 2 * kp + 1) * PXS + p];
            __half h0 = __float2half_rn(v0), h1 = __float2half_rn(v1);
            size_t off = ((size_t)b * HW + p0 + p) * 32 + kp;
            g_K2H[off] = h2u(__halves2half2(h0, h1));
            g_K2L[off] = packh2(v0 - __half2float(h0), v1 - __half2float(h1));
        }
    } else {
        // V rows (rg-1)*128 .. +127 -> g_V2 [b][256][2048], packed along hw
        for (int i = t; i < 8192; i += 256) {
            int vl = i >> 6, p2 = i & 63;
            float v0 = ST[vl * PXS + 2 * p2];
            float v1 = ST[vl * PXS + 2 * p2 + 1];
            size_t off = ((size_t)b * 256 + (rg - 1) * 128 + vl) * (HW / 2)
                       + p0 / 2 + p2;
            g_V2[off] = packh2(v0, v1);
        }
    }
#undef PJ_ISSUE
}

// ---------------------------------------------------------------------------
// fp16 flash attention — 64-query CTAs, 2 CTAs/SM; ALL fragments via ldmatrix
// x4 (Q, K, P, V pairs). cp.async addresses hoisted. (Unchanged from R16.)
// ---------------------------------------------------------------------------
#define QS2 36
#define KS2 36
#define VS2 36
#define PS2 36
#define WOFF_QH 0
#define WOFF_QL 2304
#define WOFF_KH 4608
#define WOFF_KL 6912
#define WOFF_V  9216
#define WOFF_P  18432
#define SMEM_WORDS 20736     // 82944 bytes per CTA

__global__ __launch_bounds__(256, 2) void attn_mma_kernel(float* __restrict__ Out)
{
    extern __shared__ uint32_t sm[];
    __shared__ __align__(16) float s_max[64][4];
    __shared__ float s_part[64][4];
    __shared__ float s_inv[64];

    uint32_t* PP = sm + WOFF_P;

    const uint32_t SB = smem_u32(sm);

    const int t    = threadIdx.x;
    const int w    = t >> 5;
    const int lane = t & 31;
    const int mg   = w >> 2;
    const int ng   = w & 3;
    const int m0   = mg * 32;
    const int lr   = lane >> 2;
    const int lc   = lane & 3;
    const int b    = blockIdx.y;
    const int p0   = blockIdx.x * 64;

    const uint32_t* QHg = g_Q2H + ((size_t)b * HW + p0) * 32;
    const uint32_t* QLg = g_Q2L + ((size_t)b * HW + p0) * 32;
    const uint32_t* KHg = g_K2H + (size_t)b * HW * 32;
    const uint32_t* KLg = g_K2L + (size_t)b * HW * 32;
    const uint32_t* Vg  = g_V2  + (size_t)b * DV * (HW / 2);

    const int  lq   = (lane & 7) + ((lane >> 3) & 1) * 8;
    const uint32_t colb = (uint32_t)(lane >> 4) * 16;
    const uint32_t qh_lm = SB + WOFF_QH * 4 + (uint32_t)(m0 + lq) * 144 + colb;
    const uint32_t ql_lm = SB + WOFF_QL * 4 + (uint32_t)(m0 + lq) * 144 + colb;
    const uint32_t pp_lm = SB + WOFF_P  * 4 + (uint32_t)(m0 + lq) * 144 + colb;
    const uint32_t kfrag_row = (uint32_t)(ng * 16 + (lane & 7) + ((lane >> 4) & 1) * 8);
    const uint32_t kfrag_col = (uint32_t)((lane >> 3) & 1) * 16;
    const uint32_t kh_lm = SB + WOFF_KH * 4 + kfrag_row * 144 + kfrag_col;
    const uint32_t kl_lm = SB + WOFF_KL * 4 + kfrag_row * 144 + kfrag_col;
    const uint32_t vfrag_row = (uint32_t)(ng * 64 + (lane & 7) + ((lane >> 4) & 1) * 8);
    const uint32_t vv4_lm = SB + WOFF_V * 4 + vfrag_row * 144 + kfrag_col;

    // ---- hoisted cp.async per-thread invariants ----
    const uint32_t qk_rc  = (uint32_t)((t >> 3) * 36 + (t & 7) * 4) * 4;
    const uint32_t qk_src = (uint32_t)((t >> 3) * 32 + (t & 7) * 4);
    const uint32_t v_src0 = (uint32_t)((t >> 3) * (HW / 2) + (t & 7) * 4);
    const uint32_t qh_d0 = SB + WOFF_QH * 4 + qk_rc;
    const uint32_t ql_d0 = SB + WOFF_QL * 4 + qk_rc;
    const uint32_t kh_d0 = SB + WOFF_KH * 4 + qk_rc;
    const uint32_t kl_d0 = SB + WOFF_KL * 4 + qk_rc;
    const uint32_t vv_d0 = SB + WOFF_V * 4 + qk_rc;

    // ---- prologue: Q group, K[0] group, V[0] group ----
    {
        cpa16(qh_d0,                 QHg + qk_src);
        cpa16(qh_d0 + 32 * 36 * 4,   QHg + qk_src + 32 * 32);
        cpa16(ql_d0,                 QLg + qk_src);
        cpa16(ql_d0 + 32 * 36 * 4,   QLg + qk_src + 32 * 32);
        CP_COMMIT();
        cpa16(kh_d0,                 KHg + qk_src);
        cpa16(kh_d0 + 32 * 36 * 4,   KHg + qk_src + 32 * 32);
        cpa16(kl_d0,                 KLg + qk_src);
        cpa16(kl_d0 + 32 * 36 * 4,   KLg + qk_src + 32 * 32);
        CP_COMMIT();
#pragma unroll
        for (int j = 0; j < 8; j++)
            cpa16(vv_d0 + (uint32_t)j * 32 * 36 * 4,
                  Vg + v_src0 + (uint32_t)j * 32 * (HW / 2));
        CP_COMMIT();
    }

    float o[2][8][4];
#pragma unroll
    for (int mt = 0; mt < 2; mt++)
#pragma unroll
        for (int vt = 0; vt < 8; vt++)
#pragma unroll
            for (int j = 0; j < 4; j++) o[mt][vt][j] = 0.f;
    float rs[4]   = {0.f, 0.f, 0.f, 0.f};
    float runm[4] = {-1e30f, -1e30f, -1e30f, -1e30f};

    uint32_t koff = 64 * 32;
    uint32_t voff = 32;

    for (int kt = 0; kt < 64; kt++) {
        CP_WAIT(1);
        __syncthreads();

        // ---- S = Qh*Kh + Qh*Kl + Ql*Kh (fp16 split, fp32 accum) ----
        float c[2][2][4];
#pragma unroll
        for (int mt = 0; mt < 2; mt++)
#pragma unroll
            for (int nt = 0; nt < 2; nt++)
#pragma unroll
                for (int j = 0; j < 4; j++) c[mt][nt][j] = 0.f;

#pragma unroll
        for (int it = 0; it < 4; it++) {
            uint32_t ah[2][4], al[2][4];
#pragma unroll
            for (int mt = 0; mt < 2; mt++) {
                ldsm_x4(ah[mt], qh_lm + (uint32_t)mt * 2304 + (uint32_t)it * 32);
                ldsm_x4(al[mt], ql_lm + (uint32_t)mt * 2304 + (uint32_t)it * 32);
            }
            uint32_t kh4[4], kl4[4];
            ldsm_x4(kh4, kh_lm + (uint32_t)it * 32);
            ldsm_x4(kl4, kl_lm + (uint32_t)it * 32);
#pragma unroll
            for (int nt = 0; nt < 2; nt++) {
                uint32_t bh0 = kh4[nt * 2], bh1 = kh4[nt * 2 + 1];
                uint32_t bl0 = kl4[nt * 2], bl1 = kl4[nt * 2 + 1];
#pragma unroll
                for (int mt = 0; mt < 2; mt++) {
                    mma_f16(c[mt][nt], ah[mt], bh0, bh1);
                    mma_f16(c[mt][nt], ah[mt], bl0, bl1);
                    mma_f16(c[mt][nt], al[mt], bh0, bh1);
                }
            }
        }

        // ---- warp-partial row max -> smem ----
#pragma unroll
        for (int mt = 0; mt < 2; mt++) {
            float mx0 = fmaxf(fmaxf(c[mt][0][0], c[mt][0][1]),
                              fmaxf(c[mt][1][0], c[mt][1][1]));
            float mx1 = fmaxf(fmaxf(c[mt][0][2], c[mt][0][3]),
                              fmaxf(c[mt][1][2], c[mt][1][3]));
            mx0 = fmaxf(mx0, __shfl_xor_sync(0xffffffffu, mx0, 1));
            mx0 = fmaxf(mx0, __shfl_xor_sync(0xffffffffu, mx0, 2));
            mx1 = fmaxf(mx1, __shfl_xor_sync(0xffffffffu, mx1, 1));
            mx1 = fmaxf(mx1, __shfl_xor_sync(0xffffffffu, mx1, 2));
            if (lc == 0) {
                s_max[m0 + mt * 16 + lr][ng]     = mx0;
                s_max[m0 + mt * 16 + lr + 8][ng] = mx1;
            }
        }
        __syncthreads();

        // ---- issue K[kt+1] ----
        if (kt < 63) {
            cpa16(kh_d0,               KHg + qk_src + koff);
            cpa16(kh_d0 + 32 * 36 * 4, KHg + qk_src + koff + 32 * 32);
            cpa16(kl_d0,               KLg + qk_src + koff);
            cpa16(kl_d0 + 32 * 36 * 4, KLg + qk_src + koff + 32 * 32);
            CP_COMMIT();
            koff += 64 * 32;
        }

        // ---- tile max, conditional online rescale (log2 domain) ----
        float nm[4], corr[4];
#pragma unroll
        for (int s = 0; s < 4; s++) {
            const int row = m0 + (s >> 1) * 16 + (s & 1) * 8 + lr;
            float4 mv = *(const float4*)&s_max[row][0];
            float tmax = fmaxf(fmaxf(mv.x, mv.y), fmaxf(mv.z, mv.w));
            if (tmax > runm[s]) {
                nm[s] = tmax;
                corr[s] = ex2f(runm[s] - tmax);
                rs[s] *= corr[s];
                runm[s] = tmax;
            } else {
                nm[s] = runm[s];
                corr[s] = 1.f;
            }
        }
#pragma unroll
        for (int mt = 0; mt < 2; mt++) {
            if (corr[mt * 2] != 1.f || corr[mt * 2 + 1] != 1.f) {
#pragma unroll
                for (int vt = 0; vt < 8; vt++) {
                    o[mt][vt][0] *= corr[mt * 2];
                    o[mt][vt][1] *= corr[mt * 2];
                    o[mt][vt][2] *= corr[mt * 2 + 1];
                    o[mt][vt][3] *= corr[mt * 2 + 1];
                }
            }
        }

        // ---- exp2, P -> SMEM fp16x2, rowsums ----
#pragma unroll
        for (int mt = 0; mt < 2; mt++) {
            const int row = m0 + mt * 16 + lr;
            const float nm0 = nm[mt * 2], nm1 = nm[mt * 2 + 1];
#pragma unroll
            for (int nt = 0; nt < 2; nt++) {
                const int np = ng * 8 + nt * 4 + lc;
                float e0 = ex2f(c[mt][nt][0] - nm0);
                float e1 = ex2f(c[mt][nt][1] - nm0);
                float e2 = ex2f(c[mt][nt][2] - nm1);
                float e3 = ex2f(c[mt][nt][3] - nm1);
                PP[row * PS2 + np]       = packh2(e0, e1);
                PP[(row + 8) * PS2 + np] = packh2(e2, e3);
                rs[mt * 2 + 0] += e0 + e1;
                rs[mt * 2 + 1] += e2 + e3;
            }
        }

        // ---- wait V[kt] (K[kt+1] stays in flight), make V+P visible ----
        if (kt < 63) { CP_WAIT(1); } else { CP_WAIT(0); }
        __syncthreads();

        // ---- O += P * V^T (all-x4 ldmatrix fragments) ----
#pragma unroll
        for (int it = 0; it < 4; it++) {
            uint32_t a[2][4];
#pragma unroll
            for (int mt = 0; mt < 2; mt++)
                ldsm_x4(a[mt], pp_lm + (uint32_t)mt * 2304 + (uint32_t)it * 32);
#pragma unroll
            for (int vt2 = 0; vt2 < 4; vt2++) {
                uint32_t v4[4];
                ldsm_x4(v4, vv4_lm + (uint32_t)vt2 * 2304 + (uint32_t)it * 32);
                mma_f16(o[0][2 * vt2],     a[0], v4[0], v4[1]);
                mma_f16(o[1][2 * vt2],     a[1], v4[0], v4[1]);
                mma_f16(o[0][2 * vt2 + 1], a[0], v4[2], v4[3]);
                mma_f16(o[1][2 * vt2 + 1], a[1], v4[2], v4[3]);
            }
        }

        // ---- V/P consumed; issue V[kt+1] ----
        __syncthreads();
        if (kt < 63) {
#pragma unroll
            for (int j = 0; j < 8; j++)
                cpa16(vv_d0 + (uint32_t)j * 32 * 36 * 4,
                      Vg + v_src0 + voff + (uint32_t)j * 32 * (HW / 2));
            CP_COMMIT();
            voff += 32;
        }
    }

    // ---- rowsum reduction across lanes and ng groups ----
#pragma unroll
    for (int i = 0; i < 4; i++) {
        rs[i] += __shfl_xor_sync(0xffffffffu, rs[i], 1);
        rs[i] += __shfl_xor_sync(0xffffffffu, rs[i], 2);
    }
    if (lc == 0) {
#pragma unroll
        for (int i = 0; i < 4; i++) {
            int row = m0 + (i >> 1) * 16 + (i & 1) * 8 + lr;
            s_part[row][ng] = rs[i];
        }
    }
    __syncthreads();
    if (t < 64)
        s_inv[t] = 1.0f / (s_part[t][0] + s_part[t][1] + s_part[t][2] + s_part[t][3]);
    __syncthreads();

    // ---- normalize + store ----
    float* Ob = Out + (size_t)b * DV * HW;
#pragma unroll
    for (int mt = 0; mt < 2; mt++) {
        const int r = m0 + mt * 16 + lr;
        const float inv0 = s_inv[r];
        const float inv1 = s_inv[r + 8];
#pragma unroll
        for (int vt = 0; vt < 8; vt++) {
            const int v = ng * 64 + vt * 8 + 2 * lc;
            Ob[(size_t)v * HW + p0 + r]           = o[mt][vt][0] * inv0;
            Ob[(size_t)(v + 1) * HW + p0 + r]     = o[mt][vt][1] * inv0;
            Ob[(size_t)v * HW + p0 + r + 8]       = o[mt][vt][2] * inv1;
            Ob[(size_t)(v + 1) * HW + p0 + r + 8] = o[mt][vt][3] * inv1;
        }
    }
}

// ---------------------------------------------------------------------------
extern "C" void kernel_launch(void* const* d_in, const int* in_sizes, int n_in,
                              void* d_out, int out_size)
{
    const float* x  = (const float*)d_in[0];
    const float* qw = (const float*)d_in[1];
    const float* kw = (const float*)d_in[2];
    const float* vw = (const float*)d_in[3];
    float* out = (float*)d_out;

    prep_all<<<192 + 16 * 128 * NB, 256>>>(x, qw, kw, vw);

    const size_t pj_smem = (size_t)PJ_SMEM_WORDS * 4;
    cudaFuncSetAttribute(proj_mma,
                         cudaFuncAttributeMaxDynamicSharedMemorySize,
                         (int)pj_smem);
    proj_mma<<<dim3(32, 3, NB), 256, pj_smem>>>();

    const size_t smem_bytes = (size_t)SMEM_WORDS * 4;
    cudaFuncSetAttribute(attn_mma_kernel,
                         cudaFuncAttributeMaxDynamicSharedMemorySize,
                         (int)smem_bytes);
    attn_mma_kernel<<<dim3(64, NB), 256, smem_bytes>>>(out);
}